// round 7
// baseline (speedup 1.0000x reference)
#include <cuda_runtime.h>
#include <cuda_bf16.h>
#include <cstdint>
#include <math.h>

// Problem constants (fixed for this dataset)
#define MAXN 50000
#define MAXE 800000
#define MAXG 512
#define HID  256

// ---------------------------------------------------------------------------
// Scratch (__device__ globals). Arrays needing zero at entry are re-zeroed by
// cleanup_kernel at the END of each call (statics start zeroed on first call).
__device__ float g_bufB[(size_t)MAXN * HID];   // layer-1 output
__device__ float g_bufC[(size_t)MAXN * HID];   // layer-2 output (no in-place RAW)
__device__ float g_dis[MAXN];
__device__ int   g_counts[MAXN];     // zeroed by cleanup
__device__ int   g_offs[MAXN + 1];
__device__ int   g_wptr[MAXN];
__device__ int   g_csr[MAXE];
__device__ float g_sums[MAXG * HID]; // zeroed by cleanup
__device__ int   g_gcnt[MAXG];       // zeroed by cleanup
__device__ int   g_pub[64];          // lookback publications, zeroed by cleanup
// split+transposed weights: [N=256 rows][K cols], K-major bf16
__device__ __nv_bfloat16 g_Wh1[256 * 128], g_Wl1[256 * 128];
__device__ __nv_bfloat16 g_Wh2[256 * 256], g_Wl2[256 * 256];
__device__ __nv_bfloat16 g_Wh3[256 * 256], g_Wl3[256 * 256];

// ---------------------------------------------------------------------------
// base-ISA tensor helpers
__device__ __forceinline__ void ldsm_x4(uint32_t& r0, uint32_t& r1, uint32_t& r2, uint32_t& r3,
                                        uint32_t addr) {
    asm volatile("ldmatrix.sync.aligned.m8n8.x4.shared.b16 {%0,%1,%2,%3}, [%4];"
                 : "=r"(r0), "=r"(r1), "=r"(r2), "=r"(r3) : "r"(addr));
}
__device__ __forceinline__ void mma_bf16(float* c, const uint32_t* a, uint32_t b0, uint32_t b1) {
    asm volatile("mma.sync.aligned.m16n8k16.row.col.f32.bf16.bf16.f32 "
                 "{%0,%1,%2,%3}, {%4,%5,%6,%7}, {%8,%9}, {%0,%1,%2,%3};"
                 : "+f"(c[0]), "+f"(c[1]), "+f"(c[2]), "+f"(c[3])
                 : "r"(a[0]), "r"(a[1]), "r"(a[2]), "r"(a[3]), "r"(b0), "r"(b1));
}
__device__ __forceinline__ void cp_async16(uint32_t smem_addr, const void* gptr) {
    asm volatile("cp.async.cg.shared.global [%0], [%1], 16;"
                 :: "r"(smem_addr), "l"(gptr) : "memory");
}
#define CP_COMMIT() asm volatile("cp.async.commit_group;" ::: "memory")
#define CP_WAIT(n)  asm volatile("cp.async.wait_group %0;" :: "n"(n) : "memory")
__device__ __forceinline__ uint32_t smem_u32(const void* p) {
    uint32_t a;
    asm("{ .reg .u64 t; cvta.to.shared.u64 t, %1; cvt.u32.u64 %0, t; }" : "=r"(a) : "l"(p));
    return a;
}
__device__ __forceinline__ void sts64(uint32_t addr, uint32_t w0, uint32_t w1) {
    asm volatile("st.shared.v2.b32 [%0], {%1,%2};" :: "r"(addr), "r"(w0), "r"(w1) : "memory");
}

// ---------------------------------------------------------------------------
// 0. setup: in-degree counts + graph node counts + all 3 weight splits (1 launch)
__global__ void setup_kernel(const int* __restrict__ ei, const int* __restrict__ batch,
                             const float* __restrict__ W1, const float* __restrict__ W2,
                             const float* __restrict__ W3, int E, int N, int K1) {
    int i = blockIdx.x * blockDim.x + threadIdx.x;
    if (i < E) { atomicAdd(&g_counts[ei[E + i]], 1); return; }
    i -= E;
    if (i < N) { atomicAdd(&g_gcnt[batch[i]], 1); return; }
    i -= N;
    int sz1 = K1 * 256, sz23 = 256 * 256;
    const float* W; __nv_bfloat16 *Wh, *Wl; int idx, K;
    if (i < sz1)               { W = W1; Wh = g_Wh1; Wl = g_Wl1; idx = i;              K = K1;  }
    else if (i < sz1 + sz23)   { W = W2; Wh = g_Wh2; Wl = g_Wl2; idx = i - sz1;        K = 256; }
    else if (i < sz1 + 2*sz23) { W = W3; Wh = g_Wh3; Wl = g_Wl3; idx = i - sz1 - sz23; K = 256; }
    else return;
    int k = idx / 256, n = idx % 256;
    float w = W[idx];
    __nv_bfloat16 hi = __float2bfloat16(w);
    Wh[n * K + k] = hi;
    Wl[n * K + k] = __float2bfloat16(w - __bfloat162float(hi));
}

// 1. single-pass decoupled-lookback exclusive scan -> offs/wptr/dis
__global__ void scan_lookback(int n) {
    int b = blockIdx.x;
    int i = b * 1024 + threadIdx.x;
    int v = (i < n) ? g_counts[i] : 0;
    __shared__ int sw[32];
    __shared__ int s_base;
    int lane = threadIdx.x & 31, wid = threadIdx.x >> 5;

    int inc = v;
    #pragma unroll
    for (int o = 1; o < 32; o <<= 1) {
        int t = __shfl_up_sync(0xffffffffu, inc, o);
        if (lane >= o) inc += t;
    }
    if (lane == 31) sw[wid] = inc;
    __syncthreads();
    if (wid == 0) {
        int t = sw[lane];
        #pragma unroll
        for (int o = 1; o < 32; o <<= 1) {
            int u = __shfl_up_sync(0xffffffffu, t, o);
            if (lane >= o) t += u;
        }
        sw[lane] = t;
    }
    __syncthreads();
    if (threadIdx.x == 0) {
        int blocktotal = sw[31];
        int prev = 0;
        if (b > 0) {
            int val;
            do { val = atomicAdd(&g_pub[b - 1], 0); } while (val == 0);
            prev = val - 1;
        }
        int incl = prev + blocktotal;
        atomicExch(&g_pub[b], incl + 1);
        s_base = prev;
        if (b == gridDim.x - 1) g_offs[n] = incl;
    }
    __syncthreads();
    int excl = s_base + inc - v + (wid > 0 ? sw[wid - 1] : 0);
    if (i < n) {
        g_offs[i] = excl;
        g_wptr[i] = excl;
        g_dis[i]  = rsqrtf(1.0f + (float)v);
    }
}

// 2. fill CSR
__global__ void fill_kernel(const int* __restrict__ ei, int E) {
    int e = blockIdx.x * blockDim.x + threadIdx.x;
    if (e < E) {
        int s = ei[e], d = ei[E + e];
        g_csr[atomicAdd(&g_wptr[d], 1)] = s;
    }
}

// ---------------------------------------------------------------------------
// 3. FUSED layer: gather(normalized agg) -> smem bf16 hi/lo -> mma GEMM -> out
//    CTA = 128 nodes, 512 threads (16 warps). A resident in smem, B streamed.
#define BSTAGE 16384   // per-stage B bytes: 256 rows * 32B * 2 (hi+lo)

template <int K, bool POOL>
__global__ void __launch_bounds__(512, 1)
layer_fused(const float* __restrict__ Hin,
            const __nv_bfloat16* __restrict__ Bh, const __nv_bfloat16* __restrict__ Bl,
            const float* __restrict__ bias, float* __restrict__ C,
            const int* __restrict__ batch, int M) {
    constexpr int AROW  = K * 2;          // bytes per smem A row (bf16)
    constexpr int ATILE = 128 * AROW;     // bytes per A buffer (hi or lo)
    constexpr int NSLAB = K / 16;
    constexpr int V = K / 128;            // float4 per lane in gather

    extern __shared__ __align__(1024) char smem[];
    uint32_t sbase = smem_u32(smem);
    uint32_t sAh = sbase, sAl = sbase + ATILE;
    uint32_t sB  = sbase + 2 * ATILE;     // 2 stages of BSTAGE

    int tid = threadIdx.x, wid = tid >> 5, lane = tid & 31;
    int m0 = blockIdx.x * 128;

    auto loadB = [&](int stage, int s) {
        int k0 = s * 16;
        uint32_t sb = sB + stage * BSTAGE;
        #pragma unroll
        for (int it = 0; it < 2; it++) {
            int c = tid + it * 512;              // 0..1023
            int isLo = c >> 9;
            int row = (c >> 1) & 255;
            int half = c & 1;
            uint32_t dst = sb + isLo * 8192 + row * 32 + ((half ^ ((row >> 2) & 1)) << 4);
            const __nv_bfloat16* src = (isLo ? Bl : Bh) + (size_t)row * K + k0 + half * 8;
            cp_async16(dst, src);
        }
        CP_COMMIT();
    };

    // prefetch B stage 0 before the gather (completes during gather)
    loadB(0, 0);

    // ---- phase 1: gather 8 nodes per warp, split to bf16 hi/lo in smem ----
    for (int i = 0; i < 8; i++) {
        int rl = wid * 8 + i;           // local A row
        int node = m0 + rl;
        float4 acc[V];
        if (node < M) {
            float di = g_dis[node];
            const float4* hrow = (const float4*)(Hin + (size_t)node * K);
            #pragma unroll
            for (int v = 0; v < V; v++) {
                float4 t = hrow[lane + v * 32];
                acc[v].x = di * t.x; acc[v].y = di * t.y;
                acc[v].z = di * t.z; acc[v].w = di * t.w;
            }
            int e0 = g_offs[node], e1 = g_offs[node + 1];
            for (int base = e0; base < e1; base += 32) {
                int e = base + lane;
                int s = 0; float w = 0.0f;
                if (e < e1) { s = g_csr[e]; w = g_dis[s]; }
                int cnt = min(32, e1 - base);
                #pragma unroll 8
                for (int j = 0; j < cnt; j++) {
                    int   sj = __shfl_sync(0xffffffffu, s, j);
                    float wj = __shfl_sync(0xffffffffu, w, j);
                    const float4* srow = (const float4*)(Hin + (size_t)sj * K);
                    #pragma unroll
                    for (int v = 0; v < V; v++) {
                        float4 t = srow[lane + v * 32];
                        acc[v].x += wj * t.x; acc[v].y += wj * t.y;
                        acc[v].z += wj * t.z; acc[v].w += wj * t.w;
                    }
                }
            }
            #pragma unroll
            for (int v = 0; v < V; v++) {
                acc[v].x *= di; acc[v].y *= di; acc[v].z *= di; acc[v].w *= di;
            }
        } else {
            #pragma unroll
            for (int v = 0; v < V; v++) acc[v] = make_float4(0.f, 0.f, 0.f, 0.f);
        }
        // split + store: lane covers k = lane*4 + v*128 .. +3 (8 bytes of bf16)
        #pragma unroll
        for (int v = 0; v < V; v++) {
            __nv_bfloat162 h01 = __floats2bfloat162_rn(acc[v].x, acc[v].y);
            __nv_bfloat162 h23 = __floats2bfloat162_rn(acc[v].z, acc[v].w);
            float2 f01 = __bfloat1622float2(h01);
            float2 f23 = __bfloat1622float2(h23);
            __nv_bfloat162 l01 = __floats2bfloat162_rn(acc[v].x - f01.x, acc[v].y - f01.y);
            __nv_bfloat162 l23 = __floats2bfloat162_rn(acc[v].z - f23.x, acc[v].w - f23.y);
            int k0 = lane * 4 + v * 128;
            int chunk = k0 >> 3;
            uint32_t off = (uint32_t)rl * AROW + ((chunk ^ (rl & 7)) << 4) + ((lane & 1) << 3);
            sts64(sAh + off, *(uint32_t*)&h01, *(uint32_t*)&h23);
            sts64(sAl + off, *(uint32_t*)&l01, *(uint32_t*)&l23);
        }
    }
    __syncthreads();

    // ---- phase 2: GEMM 128x256, warp grid 4(m)x4(n), warp tile 32x64 ----
    int wm = wid >> 2, wn = wid & 3;
    int r = lane & 15, sel = lane >> 4;

    float acc2[2][8][4];
    #pragma unroll
    for (int a = 0; a < 2; a++)
        #pragma unroll
        for (int b = 0; b < 8; b++)
            #pragma unroll
            for (int q = 0; q < 4; q++) acc2[a][b][q] = 0.0f;

    for (int s = 0; s < NSLAB; s++) {
        if (s + 1 < NSLAB) loadB((s + 1) & 1, s + 1);
        if (s + 1 < NSLAB) { CP_WAIT(1); } else { CP_WAIT(0); }
        __syncthreads();
        uint32_t sb = sB + (s & 1) * BSTAGE;

        uint32_t ah[2][4], al[2][4];
        #pragma unroll
        for (int mi = 0; mi < 2; mi++) {
            int rowA = wm * 32 + mi * 16 + r;
            int chunk = 2 * s + sel;
            uint32_t off = (uint32_t)rowA * AROW + ((chunk ^ (rowA & 7)) << 4);
            ldsm_x4(ah[mi][0], ah[mi][1], ah[mi][2], ah[mi][3], sAh + off);
            ldsm_x4(al[mi][0], al[mi][1], al[mi][2], al[mi][3], sAl + off);
        }
        #pragma unroll
        for (int h = 0; h < 2; h++) {     // two N-halves to bound registers
            uint32_t bh[2][4], bl[2][4];
            #pragma unroll
            for (int j = 0; j < 2; j++) {
                int nj = h * 2 + j;
                int rowB = wn * 64 + nj * 16 + r;
                uint32_t off = rowB * 32 + ((sel ^ ((rowB >> 2) & 1)) << 4);
                ldsm_x4(bh[j][0], bh[j][1], bh[j][2], bh[j][3], sb + off);
                ldsm_x4(bl[j][0], bl[j][1], bl[j][2], bl[j][3], sb + 8192 + off);
            }
            #pragma unroll
            for (int mi = 0; mi < 2; mi++) {
                #pragma unroll
                for (int t = 0; t < 4; t++) {
                    int j = t >> 1, hi8 = t & 1;
                    int nn = h * 4 + t;
                    uint32_t b0h = bh[j][hi8], b1h = bh[j][hi8 + 2];
                    uint32_t b0l = bl[j][hi8], b1l = bl[j][hi8 + 2];
                    mma_bf16(acc2[mi][nn], ah[mi], b0h, b1h);
                    mma_bf16(acc2[mi][nn], ah[mi], b0l, b1l);
                    mma_bf16(acc2[mi][nn], al[mi], b0h, b1h);
                }
            }
        }
        __syncthreads();
    }

    // ---- epilogue: bias + relu; store C or pool into g_sums ----
    int qr = lane >> 2, qc = lane & 3;
    #pragma unroll
    for (int nn = 0; nn < 8; nn++) {
        // nn = h*4 + t, t = j*2 + hi8 ; col = wn*64 + (h*2+j)*16 + hi8*8 + qc*2
        int hh = nn >> 2, t = nn & 3, j = t >> 1, hi8 = t & 1;
        int col = wn * 64 + (hh * 2 + j) * 16 + hi8 * 8 + qc * 2;
        float bz0 = __ldg(&bias[col]), bz1 = __ldg(&bias[col + 1]);
        #pragma unroll
        for (int mi = 0; mi < 2; mi++) {
            int row0 = m0 + wm * 32 + mi * 16 + qr;
            if (row0 < M) {
                float v0 = fmaxf(acc2[mi][nn][0] + bz0, 0.f);
                float v1 = fmaxf(acc2[mi][nn][1] + bz1, 0.f);
                if (POOL) {
                    int g = __ldg(&batch[row0]);
                    atomicAdd(&g_sums[g * HID + col],     v0);
                    atomicAdd(&g_sums[g * HID + col + 1], v1);
                } else {
                    *(float2*)(C + (size_t)row0 * 256 + col) = make_float2(v0, v1);
                }
            }
            int row1 = row0 + 8;
            if (row1 < M) {
                float v2 = fmaxf(acc2[mi][nn][2] + bz0, 0.f);
                float v3 = fmaxf(acc2[mi][nn][3] + bz1, 0.f);
                if (POOL) {
                    int g = __ldg(&batch[row1]);
                    atomicAdd(&g_sums[g * HID + col],     v2);
                    atomicAdd(&g_sums[g * HID + col + 1], v3);
                } else {
                    *(float2*)(C + (size_t)row1 * 256 + col) = make_float2(v2, v3);
                }
            }
        }
    }
}

// ---------------------------------------------------------------------------
// 4. head: mean, concat, fc1(relu), fc2 -> out[G,16]
__global__ void head_kernel(const float* __restrict__ molwt, const float* __restrict__ nrings,
                            const float* __restrict__ fcW1, const float* __restrict__ fcb1,
                            const float* __restrict__ fcW2, const float* __restrict__ fcb2,
                            float* __restrict__ out) {
    int g = blockIdx.x;
    __shared__ float hg[258];
    __shared__ float h1[196];
    int t = threadIdx.x;  // 256
    float c = fmaxf((float)g_gcnt[g], 1.0f);
    hg[t] = g_sums[g * HID + t] / c;
    if (t == 0) { hg[256] = molwt[g]; hg[257] = nrings[g]; }
    __syncthreads();
    if (t < 196) {
        float a = fcb1[t];
        #pragma unroll 4
        for (int k = 0; k < 258; k++) a += hg[k] * fcW1[k * 196 + t];
        h1[t] = fmaxf(a, 0.0f);
    }
    __syncthreads();
    if (t < 16) {
        float a = fcb2[t];
        #pragma unroll 4
        for (int k = 0; k < 196; k++) a += h1[k] * fcW2[k * 16 + t];
        out[g * 16 + t] = a;
    }
}

// 5. cleanup: restore zeroed scratch for next call
__global__ void cleanup_kernel(int n_nodes, int n_graphs) {
    int i = blockIdx.x * blockDim.x + threadIdx.x;
    int total = n_nodes + 64 + n_graphs + n_graphs * HID;
    for (; i < total; i += gridDim.x * blockDim.x) {
        if (i < n_nodes) g_counts[i] = 0;
        else if (i < n_nodes + 64) g_pub[i - n_nodes] = 0;
        else if (i < n_nodes + 64 + n_graphs) g_gcnt[i - n_nodes - 64] = 0;
        else g_sums[i - n_nodes - 64 - n_graphs] = 0.0f;
    }
}

// ---------------------------------------------------------------------------
extern "C" void kernel_launch(void* const* d_in, const int* in_sizes, int n_in,
                              void* d_out, int out_size) {
    const float* x      = (const float*)d_in[0];
    const int*   ei     = (const int*)  d_in[1];
    const int*   batch  = (const int*)  d_in[2];
    const float* molwt  = (const float*)d_in[3];
    const float* nrings = (const float*)d_in[4];
    const float* W1 = (const float*)d_in[5];
    const float* b1 = (const float*)d_in[6];
    const float* W2 = (const float*)d_in[7];
    const float* b2 = (const float*)d_in[8];
    const float* W3 = (const float*)d_in[9];
    const float* b3 = (const float*)d_in[10];
    const float* fcW1 = (const float*)d_in[11];
    const float* fcb1 = (const float*)d_in[12];
    const float* fcW2 = (const float*)d_in[13];
    const float* fcb2 = (const float*)d_in[14];

    const int N = in_sizes[2];
    const int E = in_sizes[1] / 2;
    const int G = in_sizes[3];
    const int F_IN = in_sizes[0] / N;   // 128

    __nv_bfloat16 *Wh1, *Wl1, *Wh2, *Wl2, *Wh3, *Wl3;
    float *bufB, *bufC;
    cudaGetSymbolAddress((void**)&bufB, g_bufB);
    cudaGetSymbolAddress((void**)&bufC, g_bufC);
    cudaGetSymbolAddress((void**)&Wh1, g_Wh1);
    cudaGetSymbolAddress((void**)&Wl1, g_Wl1);
    cudaGetSymbolAddress((void**)&Wh2, g_Wh2);
    cudaGetSymbolAddress((void**)&Wl2, g_Wl2);
    cudaGetSymbolAddress((void**)&Wh3, g_Wh3);
    cudaGetSymbolAddress((void**)&Wl3, g_Wl3);

    const int SMEM_K128 = 2 * (128 * 128 * 2) + 2 * BSTAGE;   //  98304
    const int SMEM_K256 = 2 * (128 * 256 * 2) + 2 * BSTAGE;   // 163840
    cudaFuncSetAttribute(layer_fused<128, false>, cudaFuncAttributeMaxDynamicSharedMemorySize, SMEM_K128);
    cudaFuncSetAttribute(layer_fused<256, false>, cudaFuncAttributeMaxDynamicSharedMemorySize, SMEM_K256);
    cudaFuncSetAttribute(layer_fused<256, true >, cudaFuncAttributeMaxDynamicSharedMemorySize, SMEM_K256);

    int nb = (N + 1023) / 1024;
    int ntile = (N + 127) / 128;
    int wtot = E + N + F_IN * 256 + 2 * 256 * 256;

    // launches 0..2: graph build + weight split
    setup_kernel<<<(wtot + 255) / 256, 256>>>(ei, batch, W1, W2, W3, E, N, F_IN);
    scan_lookback<<<nb, 1024>>>(N);
    fill_kernel<<<(E + 255) / 256, 256>>>(ei, E);

    // launch 3: fused layer 1 (the launch ncu profiles)
    layer_fused<128, false><<<ntile, 512, SMEM_K128>>>(x,    Wh1, Wl1, b1, bufB, nullptr, N);
    // layer 2: read bufB, write bufC (no in-place hazard)
    layer_fused<256, false><<<ntile, 512, SMEM_K256>>>(bufB, Wh2, Wl2, b2, bufC, nullptr, N);
    // layer 3: read bufC, pool into g_sums
    layer_fused<256, true ><<<ntile, 512, SMEM_K256>>>(bufC, Wh3, Wl3, b3, nullptr, batch, N);

    head_kernel<<<G, 256>>>(molwt, nrings, fcW1, fcb1, fcW2, fcb2, (float*)d_out);
    cleanup_kernel<<<256, 256>>>(N, G);
}

// round 8
// speedup vs baseline: 1.1380x; 1.1380x over previous
#include <cuda_runtime.h>
#include <cuda_bf16.h>
#include <cstdint>
#include <math.h>

// Problem constants (fixed for this dataset)
#define MAXN 50000
#define MAXE 800000
#define MAXG 512
#define HID  256

// ---------------------------------------------------------------------------
// Scratch (__device__ globals: allocation-free per harness rules)
__device__ __nv_bfloat16 g_Ah[(size_t)MAXN * HID];   // agg output, bf16 hi
__device__ __nv_bfloat16 g_Al[(size_t)MAXN * HID];   // agg output, bf16 lo
__device__ float g_bufB[(size_t)MAXN * HID];         // post-GEMM hidden (fp32)
__device__ float g_dis[MAXN];
__device__ int   g_counts[MAXN];
__device__ int   g_offs[MAXN + 1];
__device__ int   g_wptr[MAXN];
__device__ int   g_csr[MAXE];
__device__ float g_sums[MAXG * HID];
__device__ int   g_gcnt[MAXG];
__device__ int   g_bsum[64];                          // block sums for scan
// split+transposed weights: [N=256 rows][K cols], K-major bf16
__device__ __nv_bfloat16 g_Wh1[256 * 128], g_Wl1[256 * 128];
__device__ __nv_bfloat16 g_Wh2[256 * 256], g_Wl2[256 * 256];
__device__ __nv_bfloat16 g_Wh3[256 * 256], g_Wl3[256 * 256];

// ---------------------------------------------------------------------------
// base-ISA tensor helpers (mma.sync / ldmatrix / cp.async)
__device__ __forceinline__ void ldsm_x4(uint32_t& r0, uint32_t& r1, uint32_t& r2, uint32_t& r3,
                                        uint32_t addr) {
    asm volatile("ldmatrix.sync.aligned.m8n8.x4.shared.b16 {%0,%1,%2,%3}, [%4];"
                 : "=r"(r0), "=r"(r1), "=r"(r2), "=r"(r3) : "r"(addr));
}
__device__ __forceinline__ void mma_bf16(float* c, const uint32_t* a, uint32_t b0, uint32_t b1) {
    asm volatile("mma.sync.aligned.m16n8k16.row.col.f32.bf16.bf16.f32 "
                 "{%0,%1,%2,%3}, {%4,%5,%6,%7}, {%8,%9}, {%0,%1,%2,%3};"
                 : "+f"(c[0]), "+f"(c[1]), "+f"(c[2]), "+f"(c[3])
                 : "r"(a[0]), "r"(a[1]), "r"(a[2]), "r"(a[3]), "r"(b0), "r"(b1));
}
__device__ __forceinline__ void cp_async16(uint32_t smem_addr, const void* gptr, uint32_t src_sz) {
    asm volatile("cp.async.cg.shared.global [%0], [%1], 16, %2;"
                 :: "r"(smem_addr), "l"(gptr), "r"(src_sz) : "memory");
}
#define CP_COMMIT() asm volatile("cp.async.commit_group;" ::: "memory")
#define CP_WAIT(n)  asm volatile("cp.async.wait_group %0;" :: "n"(n) : "memory")
__device__ __forceinline__ uint32_t smem_u32(const void* p) {
    uint32_t a;
    asm("{ .reg .u64 t; cvta.to.shared.u64 t, %1; cvt.u32.u64 %0, t; }" : "=r"(a) : "l"(p));
    return a;
}

// ---------------------------------------------------------------------------
// 0. zero-init
__global__ void init_kernel(int n_nodes, int n_graphs) {
    int i = blockIdx.x * blockDim.x + threadIdx.x;
    int total = n_nodes + n_graphs + n_graphs * HID;
    for (; i < total; i += gridDim.x * blockDim.x) {
        if (i < n_nodes) g_counts[i] = 0;
        else if (i < n_nodes + n_graphs) g_gcnt[i - n_nodes] = 0;
        else g_sums[i - n_nodes - n_graphs] = 0.0f;
    }
}
// 1. in-degree
__global__ void count_kernel(const int* __restrict__ ei, int E) {
    int e = blockIdx.x * blockDim.x + threadIdx.x;
    if (e < E) atomicAdd(&g_counts[ei[E + e]], 1);
}
// 1b. per-graph node counts
__global__ void gcnt_kernel(const int* __restrict__ batch, int N) {
    int i = blockIdx.x * blockDim.x + threadIdx.x;
    if (i < N) atomicAdd(&g_gcnt[batch[i]], 1);
}
// 2a. per-block reduce -> g_bsum
__global__ void scan_p1(int n) {
    int i = blockIdx.x * 1024 + threadIdx.x;
    int v = (i < n) ? g_counts[i] : 0;
    __shared__ int sw[32];
    int lane = threadIdx.x & 31, wid = threadIdx.x >> 5;
    int s = v;
    #pragma unroll
    for (int o = 16; o > 0; o >>= 1) s += __shfl_down_sync(0xffffffffu, s, o);
    if (lane == 0) sw[wid] = s;
    __syncthreads();
    if (wid == 0) {
        int t = sw[lane];
        #pragma unroll
        for (int o = 16; o > 0; o >>= 1) t += __shfl_down_sync(0xffffffffu, t, o);
        if (lane == 0) g_bsum[blockIdx.x] = t;
    }
}
// 2b. one block scans block sums
__global__ void scan_p2(int nb, int n) {
    int lane = threadIdx.x;  // 64 threads
    __shared__ int sm[64];
    int v = (lane < nb) ? g_bsum[lane] : 0;
    sm[lane] = v;
    __syncthreads();
    #pragma unroll
    for (int d = 1; d < 64; d <<= 1) {
        int t = (lane >= d) ? sm[lane - d] : 0;
        __syncthreads();
        sm[lane] += t;
        __syncthreads();
    }
    if (lane < nb) g_bsum[lane] = sm[lane] - v;   // exclusive
    if (lane == nb - 1) g_offs[n] = sm[lane];     // total
}
// 2c. per-block inclusive scan + base -> offs/wptr/dis
__global__ void scan_p3(int n) {
    int base = g_bsum[blockIdx.x];
    int i = blockIdx.x * 1024 + threadIdx.x;
    int v = (i < n) ? g_counts[i] : 0;
    __shared__ int sw[32];
    int lane = threadIdx.x & 31, wid = threadIdx.x >> 5;
    int inc = v;
    #pragma unroll
    for (int o = 1; o < 32; o <<= 1) {
        int t = __shfl_up_sync(0xffffffffu, inc, o);
        if (lane >= o) inc += t;
    }
    if (lane == 31) sw[wid] = inc;
    __syncthreads();
    if (wid == 0) {
        int t = sw[lane];
        #pragma unroll
        for (int o = 1; o < 32; o <<= 1) {
            int u = __shfl_up_sync(0xffffffffu, t, o);
            if (lane >= o) t += u;
        }
        sw[lane] = t;
    }
    __syncthreads();
    int excl = base + inc - v + (wid > 0 ? sw[wid - 1] : 0);
    if (i < n) {
        g_offs[i] = excl;
        g_wptr[i] = excl;
        g_dis[i]  = rsqrtf(1.0f + (float)v);
    }
}
// 3. fill CSR
__global__ void fill_kernel(const int* __restrict__ ei, int E) {
    int e = blockIdx.x * blockDim.x + threadIdx.x;
    if (e < E) {
        int s = ei[e], d = ei[E + e];
        g_csr[atomicAdd(&g_wptr[d], 1)] = s;
    }
}

// ---------------------------------------------------------------------------
// 4. warp-per-node aggregation + fused bf16 hi/lo split
template <int F>
__global__ void agg_split_v2(const float* __restrict__ h,
                             __nv_bfloat16* __restrict__ oh,
                             __nv_bfloat16* __restrict__ ol, int N) {
    constexpr int V = F / 128;
    int node = blockIdx.x * (blockDim.x >> 5) + (threadIdx.x >> 5);
    int lane = threadIdx.x & 31;
    if (node >= N) return;

    float di = g_dis[node];
    float4 acc[V];
    const float4* hrow = (const float4*)(h + (size_t)node * F);
    #pragma unroll
    for (int v = 0; v < V; v++) {
        float4 t = hrow[lane + v * 32];
        acc[v].x = di * t.x; acc[v].y = di * t.y;
        acc[v].z = di * t.z; acc[v].w = di * t.w;
    }

    int e0 = g_offs[node], e1 = g_offs[node + 1];
    for (int base = e0; base < e1; base += 32) {
        int e = base + lane;
        int s = 0; float w = 0.0f;
        if (e < e1) { s = g_csr[e]; w = g_dis[s]; }
        int cnt = min(32, e1 - base);
        #pragma unroll 4
        for (int j = 0; j < cnt; j++) {
            int   sj = __shfl_sync(0xffffffffu, s, j);
            float wj = __shfl_sync(0xffffffffu, w, j);
            const float4* srow = (const float4*)(h + (size_t)sj * F);
            #pragma unroll
            for (int v = 0; v < V; v++) {
                float4 t = srow[lane + v * 32];
                acc[v].x += wj * t.x; acc[v].y += wj * t.y;
                acc[v].z += wj * t.z; acc[v].w += wj * t.w;
            }
        }
    }

    #pragma unroll
    for (int v = 0; v < V; v++) {
        float4 r;
        r.x = di * acc[v].x; r.y = di * acc[v].y;
        r.z = di * acc[v].z; r.w = di * acc[v].w;
        __nv_bfloat162 h01 = __floats2bfloat162_rn(r.x, r.y);
        __nv_bfloat162 h23 = __floats2bfloat162_rn(r.z, r.w);
        float2 f01 = __bfloat1622float2(h01);
        float2 f23 = __bfloat1622float2(h23);
        __nv_bfloat162 l01 = __floats2bfloat162_rn(r.x - f01.x, r.y - f01.y);
        __nv_bfloat162 l23 = __floats2bfloat162_rn(r.z - f23.x, r.w - f23.y);
        size_t idx = (size_t)node * F + (lane + v * 32) * 4;
        uint2 uh, ul;
        uh.x = *(uint32_t*)&h01; uh.y = *(uint32_t*)&h23;
        ul.x = *(uint32_t*)&l01; ul.y = *(uint32_t*)&l23;
        *(uint2*)(oh + idx) = uh;
        *(uint2*)(ol + idx) = ul;
    }
}

// 5. weight split + transpose: W[K,N] fp32 -> Wh/Wl [N,K] bf16 (K-major)
__global__ void wsplit_kernel(const float* __restrict__ W,
                              __nv_bfloat16* __restrict__ Wh, __nv_bfloat16* __restrict__ Wl,
                              int K, int N) {
    int idx = blockIdx.x * blockDim.x + threadIdx.x;
    if (idx < K * N) {
        int k = idx / N, n = idx % N;
        float w = W[idx];
        __nv_bfloat16 hi = __float2bfloat16(w);
        Wh[n * K + k] = hi;
        Wl[n * K + k] = __float2bfloat16(w - __bfloat162float(hi));
    }
}

// ---------------------------------------------------------------------------
// 6. tensor-core GEMM via mma.sync (3-term bf16 split), paired k-slabs:
//    each pipeline stage covers k=32 (two 16-slabs), halving barrier count.
//    CTA tile 128x128, 256 thr. Dynamic smem: 2 stages x 32KB.
#define PITCH_B 32
#define TILE_B  4096
#define SLAB_B  16384            // one k16 slab: Ah,Al,Bh,Bl tiles
#define STAGE_B (2 * SLAB_B)     // paired slabs

template <bool POOL>
__global__ void __launch_bounds__(256)
gemm_tc(const __nv_bfloat16* __restrict__ Ah, const __nv_bfloat16* __restrict__ Al,
        const __nv_bfloat16* __restrict__ Bh, const __nv_bfloat16* __restrict__ Bl,
        const float* __restrict__ bias, float* __restrict__ C,
        const int* __restrict__ batch, int M, int K) {
    extern __shared__ __align__(1024) char smem[];
    uint32_t sbase = smem_u32(smem);

    int tid = threadIdx.x;
    int wid = tid >> 5, lane = tid & 31;
    int wm = wid >> 2, wn = wid & 3;
    int m0 = blockIdx.y * 128, n0 = blockIdx.x * 128;

    float acc[4][4][4];
    #pragma unroll
    for (int i = 0; i < 4; i++)
        #pragma unroll
        for (int j = 0; j < 4; j++)
            #pragma unroll
            for (int q = 0; q < 4; q++) acc[i][j][q] = 0.0f;

    int npair = K >> 5;   // paired slabs

    // load one k16 slab into slab buffer at sb
    auto load_slab = [&](uint32_t sb, int k0) {
        #pragma unroll
        for (int i = 0; i < 4; i++) {
            int c = tid + i * 256;
            int tile = c >> 8, t = c & 255;
            int row = t >> 1, half = t & 1;
            uint32_t dst = sb + tile * TILE_B + row * PITCH_B +
                           ((half ^ ((row >> 2) & 1)) << 4);
            const __nv_bfloat16* src;
            uint32_t sz = 16;
            if (tile < 2) {
                int gr = m0 + row;
                int cr = gr < M ? gr : (M - 1);
                src = (tile == 0 ? Ah : Al) + (size_t)cr * K + k0 + half * 8;
                if (gr >= M) sz = 0;
            } else {
                src = (tile == 2 ? Bh : Bl) + (size_t)(n0 + row) * K + k0 + half * 8;
            }
            cp_async16(dst, src, sz);
        }
    };
    auto load_pair = [&](int stage, int p) {
        uint32_t sb = sbase + stage * STAGE_B;
        load_slab(sb,          p * 32);
        load_slab(sb + SLAB_B, p * 32 + 16);
        CP_COMMIT();
    };

    int r = lane & 15, sel = lane >> 4;

    // compute one k16 slab from slab buffer at sb
    auto compute_slab = [&](uint32_t sb) {
        uint32_t sAh = sb, sAl = sb + TILE_B, sBh = sb + 2 * TILE_B, sBl = sb + 3 * TILE_B;
        uint32_t ah[4][4], al[4][4];
        #pragma unroll
        for (int mi = 0; mi < 4; mi++) {
            int rowA = wm * 64 + mi * 16 + r;
            uint32_t off = rowA * PITCH_B + ((sel ^ ((rowA >> 2) & 1)) << 4);
            ldsm_x4(ah[mi][0], ah[mi][1], ah[mi][2], ah[mi][3], sAh + off);
            ldsm_x4(al[mi][0], al[mi][1], al[mi][2], al[mi][3], sAl + off);
        }
        uint32_t bh[2][4], bl[2][4];
        #pragma unroll
        for (int nj = 0; nj < 2; nj++) {
            int rowB = wn * 32 + nj * 16 + r;
            uint32_t off = rowB * PITCH_B + ((sel ^ ((rowB >> 2) & 1)) << 4);
            ldsm_x4(bh[nj][0], bh[nj][1], bh[nj][2], bh[nj][3], sBh + off);
            ldsm_x4(bl[nj][0], bl[nj][1], bl[nj][2], bl[nj][3], sBl + off);
        }
        #pragma unroll
        for (int mi = 0; mi < 4; mi++) {
            #pragma unroll
            for (int nn = 0; nn < 4; nn++) {
                int nj = nn >> 1, hi8 = nn & 1;
                uint32_t b0h = bh[nj][hi8], b1h = bh[nj][hi8 + 2];
                uint32_t b0l = bl[nj][hi8], b1l = bl[nj][hi8 + 2];
                mma_bf16(acc[mi][nn], ah[mi], b0h, b1h);
                mma_bf16(acc[mi][nn], ah[mi], b0l, b1l);
                mma_bf16(acc[mi][nn], al[mi], b0h, b1h);
            }
        }
    };

    load_pair(0, 0);

    for (int p = 0; p < npair; p++) {
        if (p + 1 < npair) load_pair((p + 1) & 1, p + 1);
        if (p + 1 < npair) { CP_WAIT(1); } else { CP_WAIT(0); }
        __syncthreads();
        uint32_t sb = sbase + (p & 1) * STAGE_B;
        compute_slab(sb);
        compute_slab(sb + SLAB_B);
        __syncthreads();
    }

    // epilogue
    int qr = lane >> 2, qc = lane & 3;
    #pragma unroll
    for (int nn = 0; nn < 4; nn++) {
        int col = n0 + wn * 32 + (nn >> 1) * 16 + (nn & 1) * 8 + qc * 2;
        float bz0 = __ldg(&bias[col]), bz1 = __ldg(&bias[col + 1]);
        #pragma unroll
        for (int mi = 0; mi < 4; mi++) {
            int row0 = m0 + wm * 64 + mi * 16 + qr;
            if (row0 < M) {
                float v0 = fmaxf(acc[mi][nn][0] + bz0, 0.f);
                float v1 = fmaxf(acc[mi][nn][1] + bz1, 0.f);
                if (POOL) {
                    int g = __ldg(&batch[row0]);
                    atomicAdd(&g_sums[g * HID + col],     v0);
                    atomicAdd(&g_sums[g * HID + col + 1], v1);
                } else {
                    *(float2*)(C + (size_t)row0 * 256 + col) = make_float2(v0, v1);
                }
            }
            int row1 = row0 + 8;
            if (row1 < M) {
                float v2 = fmaxf(acc[mi][nn][2] + bz0, 0.f);
                float v3 = fmaxf(acc[mi][nn][3] + bz1, 0.f);
                if (POOL) {
                    int g = __ldg(&batch[row1]);
                    atomicAdd(&g_sums[g * HID + col],     v2);
                    atomicAdd(&g_sums[g * HID + col + 1], v3);
                } else {
                    *(float2*)(C + (size_t)row1 * 256 + col) = make_float2(v2, v3);
                }
            }
        }
    }
}

// ---------------------------------------------------------------------------
// 7. head: mean, concat, fc1(relu), fc2 -> out[G,16]
__global__ void head_kernel(const float* __restrict__ molwt, const float* __restrict__ nrings,
                            const float* __restrict__ fcW1, const float* __restrict__ fcb1,
                            const float* __restrict__ fcW2, const float* __restrict__ fcb2,
                            float* __restrict__ out) {
    int g = blockIdx.x;
    __shared__ float hg[258];
    __shared__ float h1[196];
    int t = threadIdx.x;  // 256
    float c = fmaxf((float)g_gcnt[g], 1.0f);
    hg[t] = g_sums[g * HID + t] / c;
    if (t == 0) { hg[256] = molwt[g]; hg[257] = nrings[g]; }
    __syncthreads();
    if (t < 196) {
        float a = fcb1[t];
        #pragma unroll 4
        for (int k = 0; k < 258; k++) a += hg[k] * fcW1[k * 196 + t];
        h1[t] = fmaxf(a, 0.0f);
    }
    __syncthreads();
    if (t < 16) {
        float a = fcb2[t];
        #pragma unroll 4
        for (int k = 0; k < 196; k++) a += h1[k] * fcW2[k * 16 + t];
        out[g * 16 + t] = a;
    }
}

// ---------------------------------------------------------------------------
extern "C" void kernel_launch(void* const* d_in, const int* in_sizes, int n_in,
                              void* d_out, int out_size) {
    const float* x      = (const float*)d_in[0];
    const int*   ei     = (const int*)  d_in[1];
    const int*   batch  = (const int*)  d_in[2];
    const float* molwt  = (const float*)d_in[3];
    const float* nrings = (const float*)d_in[4];
    const float* W1 = (const float*)d_in[5];
    const float* b1 = (const float*)d_in[6];
    const float* W2 = (const float*)d_in[7];
    const float* b2 = (const float*)d_in[8];
    const float* W3 = (const float*)d_in[9];
    const float* b3 = (const float*)d_in[10];
    const float* fcW1 = (const float*)d_in[11];
    const float* fcb1 = (const float*)d_in[12];
    const float* fcW2 = (const float*)d_in[13];
    const float* fcb2 = (const float*)d_in[14];

    const int N = in_sizes[2];
    const int E = in_sizes[1] / 2;
    const int G = in_sizes[3];
    const int F_IN = in_sizes[0] / N;   // 128

    __nv_bfloat16 *Ah, *Al, *Wh1, *Wl1, *Wh2, *Wl2, *Wh3, *Wl3;
    float* bufB;
    cudaGetSymbolAddress((void**)&Ah, g_Ah);
    cudaGetSymbolAddress((void**)&Al, g_Al);
    cudaGetSymbolAddress((void**)&bufB, g_bufB);
    cudaGetSymbolAddress((void**)&Wh1, g_Wh1);
    cudaGetSymbolAddress((void**)&Wl1, g_Wl1);
    cudaGetSymbolAddress((void**)&Wh2, g_Wh2);
    cudaGetSymbolAddress((void**)&Wl2, g_Wl2);
    cudaGetSymbolAddress((void**)&Wh3, g_Wh3);
    cudaGetSymbolAddress((void**)&Wl3, g_Wl3);

    const int GEMM_SMEM = 2 * STAGE_B;   // 65536
    cudaFuncSetAttribute(gemm_tc<false>, cudaFuncAttributeMaxDynamicSharedMemorySize, GEMM_SMEM);
    cudaFuncSetAttribute(gemm_tc<true >, cudaFuncAttributeMaxDynamicSharedMemorySize, GEMM_SMEM);

    // graph structure
    int nb = (N + 1023) / 1024;
    init_kernel<<<256, 256>>>(N, G);
    count_kernel<<<(E + 255) / 256, 256>>>(ei, E);
    gcnt_kernel<<<(N + 255) / 256, 256>>>(batch, N);
    scan_p1<<<nb, 1024>>>(N);
    scan_p2<<<1, 64>>>(nb, N);
    scan_p3<<<nb, 1024>>>(N);
    fill_kernel<<<(E + 255) / 256, 256>>>(ei, E);

    // weight splits (transposed, K-major)
    wsplit_kernel<<<(F_IN * 256 + 255) / 256, 256>>>(W1, Wh1, Wl1, F_IN, 256);
    wsplit_kernel<<<(256 * 256 + 255) / 256, 256>>>(W2, Wh2, Wl2, 256, 256);
    wsplit_kernel<<<(256 * 256 + 255) / 256, 256>>>(W3, Wh3, Wl3, 256, 256);

    dim3 ggrid(2, (N + 127) / 128);
    int aggblocks = (N + 7) / 8;   // 8 warps / block

    // layer 1
    agg_split_v2<128><<<aggblocks, 256>>>(x, Ah, Al, N);
    gemm_tc<false><<<ggrid, 256, GEMM_SMEM>>>(Ah, Al, Wh1, Wl1, b1, bufB, nullptr, N, F_IN);
    // layer 2
    agg_split_v2<256><<<aggblocks, 256>>>(bufB, Ah, Al, N);
    gemm_tc<false><<<ggrid, 256, GEMM_SMEM>>>(Ah, Al, Wh2, Wl2, b2, bufB, nullptr, N, HID);
    // layer 3 (pooling fused into epilogue)
    agg_split_v2<256><<<aggblocks, 256>>>(bufB, Ah, Al, N);
    gemm_tc<true><<<ggrid, 256, GEMM_SMEM>>>(Ah, Al, Wh3, Wl3, b3, nullptr, batch, N, HID);

    // pooling mean + head
    head_kernel<<<G, 256>>>(molwt, nrings, fcW1, fcb1, fcW2, fcb2, (float*)d_out);
}

// round 9
// speedup vs baseline: 1.3046x; 1.1465x over previous
#include <cuda_runtime.h>
#include <cuda_fp16.h>
#include <cstdint>
#include <math.h>

// Problem constants (fixed for this dataset)
#define MAXN 50000
#define MAXE 800000
#define MAXG 512
#define HID  256

// ---------------------------------------------------------------------------
// Scratch (__device__ globals: allocation-free per harness rules)
__device__ __half g_A[(size_t)MAXN * HID];            // agg output, fp16
__device__ float g_bufB[(size_t)MAXN * HID];          // post-GEMM hidden (fp32)
__device__ float g_dis[MAXN];
__device__ int   g_counts[MAXN];
__device__ int   g_offs[MAXN + 1];
__device__ int   g_wptr[MAXN];
__device__ int   g_csr[MAXE];
__device__ float g_sums[MAXG * HID];
__device__ int   g_gcnt[MAXG];
__device__ int   g_bsum[64];                          // block sums for scan
// split+transposed weights: [N=256 rows][K cols], K-major fp16 hi/lo
__device__ __half g_Wh1[256 * 128], g_Wl1[256 * 128];
__device__ __half g_Wh2[256 * 256], g_Wl2[256 * 256];
__device__ __half g_Wh3[256 * 256], g_Wl3[256 * 256];

// ---------------------------------------------------------------------------
// base-ISA tensor helpers (mma.sync / ldmatrix / cp.async)
__device__ __forceinline__ void ldsm_x4(uint32_t& r0, uint32_t& r1, uint32_t& r2, uint32_t& r3,
                                        uint32_t addr) {
    asm volatile("ldmatrix.sync.aligned.m8n8.x4.shared.b16 {%0,%1,%2,%3}, [%4];"
                 : "=r"(r0), "=r"(r1), "=r"(r2), "=r"(r3) : "r"(addr));
}
__device__ __forceinline__ void mma_fp16(float* c, const uint32_t* a, uint32_t b0, uint32_t b1) {
    asm volatile("mma.sync.aligned.m16n8k16.row.col.f32.f16.f16.f32 "
                 "{%0,%1,%2,%3}, {%4,%5,%6,%7}, {%8,%9}, {%0,%1,%2,%3};"
                 : "+f"(c[0]), "+f"(c[1]), "+f"(c[2]), "+f"(c[3])
                 : "r"(a[0]), "r"(a[1]), "r"(a[2]), "r"(a[3]), "r"(b0), "r"(b1));
}
__device__ __forceinline__ void cp_async16(uint32_t smem_addr, const void* gptr, uint32_t src_sz) {
    asm volatile("cp.async.cg.shared.global [%0], [%1], 16, %2;"
                 :: "r"(smem_addr), "l"(gptr), "r"(src_sz) : "memory");
}
#define CP_COMMIT() asm volatile("cp.async.commit_group;" ::: "memory")
#define CP_WAIT(n)  asm volatile("cp.async.wait_group %0;" :: "n"(n) : "memory")
__device__ __forceinline__ uint32_t smem_u32(const void* p) {
    uint32_t a;
    asm("{ .reg .u64 t; cvta.to.shared.u64 t, %1; cvt.u32.u64 %0, t; }" : "=r"(a) : "l"(p));
    return a;
}

// ---------------------------------------------------------------------------
// 0. zero-init
__global__ void init_kernel(int n_nodes, int n_graphs) {
    int i = blockIdx.x * blockDim.x + threadIdx.x;
    int total = n_nodes + n_graphs + n_graphs * HID;
    for (; i < total; i += gridDim.x * blockDim.x) {
        if (i < n_nodes) g_counts[i] = 0;
        else if (i < n_nodes + n_graphs) g_gcnt[i - n_nodes] = 0;
        else g_sums[i - n_nodes - n_graphs] = 0.0f;
    }
}
// 1. in-degree
__global__ void count_kernel(const int* __restrict__ ei, int E) {
    int e = blockIdx.x * blockDim.x + threadIdx.x;
    if (e < E) atomicAdd(&g_counts[ei[E + e]], 1);
}
// 1b. per-graph node counts
__global__ void gcnt_kernel(const int* __restrict__ batch, int N) {
    int i = blockIdx.x * blockDim.x + threadIdx.x;
    if (i < N) atomicAdd(&g_gcnt[batch[i]], 1);
}
// 2a. per-block reduce -> g_bsum
__global__ void scan_p1(int n) {
    int i = blockIdx.x * 1024 + threadIdx.x;
    int v = (i < n) ? g_counts[i] : 0;
    __shared__ int sw[32];
    int lane = threadIdx.x & 31, wid = threadIdx.x >> 5;
    int s = v;
    #pragma unroll
    for (int o = 16; o > 0; o >>= 1) s += __shfl_down_sync(0xffffffffu, s, o);
    if (lane == 0) sw[wid] = s;
    __syncthreads();
    if (wid == 0) {
        int t = sw[lane];
        #pragma unroll
        for (int o = 16; o > 0; o >>= 1) t += __shfl_down_sync(0xffffffffu, t, o);
        if (lane == 0) g_bsum[blockIdx.x] = t;
    }
}
// 2b. one block scans block sums
__global__ void scan_p2(int nb, int n) {
    int lane = threadIdx.x;  // 64 threads
    __shared__ int sm[64];
    int v = (lane < nb) ? g_bsum[lane] : 0;
    sm[lane] = v;
    __syncthreads();
    #pragma unroll
    for (int d = 1; d < 64; d <<= 1) {
        int t = (lane >= d) ? sm[lane - d] : 0;
        __syncthreads();
        sm[lane] += t;
        __syncthreads();
    }
    if (lane < nb) g_bsum[lane] = sm[lane] - v;   // exclusive
    if (lane == nb - 1) g_offs[n] = sm[lane];     // total
}
// 2c. per-block inclusive scan + base -> offs/wptr/dis
__global__ void scan_p3(int n) {
    int base = g_bsum[blockIdx.x];
    int i = blockIdx.x * 1024 + threadIdx.x;
    int v = (i < n) ? g_counts[i] : 0;
    __shared__ int sw[32];
    int lane = threadIdx.x & 31, wid = threadIdx.x >> 5;
    int inc = v;
    #pragma unroll
    for (int o = 1; o < 32; o <<= 1) {
        int t = __shfl_up_sync(0xffffffffu, inc, o);
        if (lane >= o) inc += t;
    }
    if (lane == 31) sw[wid] = inc;
    __syncthreads();
    if (wid == 0) {
        int t = sw[lane];
        #pragma unroll
        for (int o = 1; o < 32; o <<= 1) {
            int u = __shfl_up_sync(0xffffffffu, t, o);
            if (lane >= o) t += u;
        }
        sw[lane] = t;
    }
    __syncthreads();
    int excl = base + inc - v + (wid > 0 ? sw[wid - 1] : 0);
    if (i < n) {
        g_offs[i] = excl;
        g_wptr[i] = excl;
        g_dis[i]  = rsqrtf(1.0f + (float)v);
    }
}
// 3. fill CSR
__global__ void fill_kernel(const int* __restrict__ ei, int E) {
    int e = blockIdx.x * blockDim.x + threadIdx.x;
    if (e < E) {
        int s = ei[e], d = ei[E + e];
        g_csr[atomicAdd(&g_wptr[d], 1)] = s;
    }
}

// ---------------------------------------------------------------------------
// 4. warp-per-node aggregation + fp16 convert (single output array)
template <int F>
__global__ void agg_split_v2(const float* __restrict__ h,
                             __half* __restrict__ oh, int N) {
    constexpr int V = F / 128;
    int node = blockIdx.x * (blockDim.x >> 5) + (threadIdx.x >> 5);
    int lane = threadIdx.x & 31;
    if (node >= N) return;

    float di = g_dis[node];
    float4 acc[V];
    const float4* hrow = (const float4*)(h + (size_t)node * F);
    #pragma unroll
    for (int v = 0; v < V; v++) {
        float4 t = hrow[lane + v * 32];
        acc[v].x = di * t.x; acc[v].y = di * t.y;
        acc[v].z = di * t.z; acc[v].w = di * t.w;
    }

    int e0 = g_offs[node], e1 = g_offs[node + 1];
    for (int base = e0; base < e1; base += 32) {
        int e = base + lane;
        int s = 0; float w = 0.0f;
        if (e < e1) { s = g_csr[e]; w = g_dis[s]; }
        int cnt = min(32, e1 - base);
        #pragma unroll 4
        for (int j = 0; j < cnt; j++) {
            int   sj = __shfl_sync(0xffffffffu, s, j);
            float wj = __shfl_sync(0xffffffffu, w, j);
            const float4* srow = (const float4*)(h + (size_t)sj * F);
            #pragma unroll
            for (int v = 0; v < V; v++) {
                float4 t = srow[lane + v * 32];
                acc[v].x += wj * t.x; acc[v].y += wj * t.y;
                acc[v].z += wj * t.z; acc[v].w += wj * t.w;
            }
        }
    }

    #pragma unroll
    for (int v = 0; v < V; v++) {
        __half2 h01 = __floats2half2_rn(di * acc[v].x, di * acc[v].y);
        __half2 h23 = __floats2half2_rn(di * acc[v].z, di * acc[v].w);
        size_t idx = (size_t)node * F + (lane + v * 32) * 4;
        uint2 uh;
        uh.x = *(uint32_t*)&h01; uh.y = *(uint32_t*)&h23;
        *(uint2*)(oh + idx) = uh;
    }
}

// 5. weight split + transpose: W[K,N] fp32 -> Wh/Wl [N,K] fp16 (K-major)
__global__ void wsplit_kernel(const float* __restrict__ W,
                              __half* __restrict__ Wh, __half* __restrict__ Wl,
                              int K, int N) {
    int idx = blockIdx.x * blockDim.x + threadIdx.x;
    if (idx < K * N) {
        int k = idx / N, n = idx % N;
        float w = W[idx];
        __half hi = __float2half_rn(w);
        Wh[n * K + k] = hi;
        Wl[n * K + k] = __float2half_rn(w - __half2float(hi));
    }
}

// ---------------------------------------------------------------------------
// 6. tensor-core GEMM via fp16 mma.sync, 2-term weight split:
//    C = relu( A_fp16 @ (Bh + Bl)^T + bias ).  B stored [N,K] K-major fp16.
//    CTA 128x128, 256 thr, paired k16 slabs per stage (k=32), double buffer.
#define PITCH_B 32
#define TILE_B  4096
#define SLAB_B  12288            // one k16 slab: A, Bh, Bl tiles
#define STAGE_B (2 * SLAB_B)     // paired slabs

template <bool POOL>
__global__ void __launch_bounds__(256)
gemm_tc(const __half* __restrict__ A,
        const __half* __restrict__ Bh, const __half* __restrict__ Bl,
        const float* __restrict__ bias, float* __restrict__ C,
        const int* __restrict__ batch, int M, int K) {
    extern __shared__ __align__(1024) char smem[];
    uint32_t sbase = smem_u32(smem);

    int tid = threadIdx.x;
    int wid = tid >> 5, lane = tid & 31;
    int wm = wid >> 2, wn = wid & 3;
    int m0 = blockIdx.y * 128, n0 = blockIdx.x * 128;

    float acc[4][4][4];
    #pragma unroll
    for (int i = 0; i < 4; i++)
        #pragma unroll
        for (int j = 0; j < 4; j++)
            #pragma unroll
            for (int q = 0; q < 4; q++) acc[i][j][q] = 0.0f;

    int npair = K >> 5;

    // load one k16 slab (tiles: 0=A, 1=Bh, 2=Bl) into slab buffer at sb
    auto load_slab = [&](uint32_t sb, int k0) {
        #pragma unroll
        for (int i = 0; i < 3; i++) {
            int c = tid + i * 256;
            int tile = c >> 8, t = c & 255;
            int row = t >> 1, half = t & 1;
            uint32_t dst = sb + tile * TILE_B + row * PITCH_B +
                           ((half ^ ((row >> 2) & 1)) << 4);
            const __half* src;
            uint32_t sz = 16;
            if (tile == 0) {
                int gr = m0 + row;
                int cr = gr < M ? gr : (M - 1);
                src = A + (size_t)cr * K + k0 + half * 8;
                if (gr >= M) sz = 0;
            } else {
                src = (tile == 1 ? Bh : Bl) + (size_t)(n0 + row) * K + k0 + half * 8;
            }
            cp_async16(dst, src, sz);
        }
    };
    auto load_pair = [&](int stage, int p) {
        uint32_t sb = sbase + stage * STAGE_B;
        load_slab(sb,          p * 32);
        load_slab(sb + SLAB_B, p * 32 + 16);
        CP_COMMIT();
    };

    int r = lane & 15, sel = lane >> 4;

    auto compute_slab = [&](uint32_t sb) {
        uint32_t sA = sb, sBh = sb + TILE_B, sBl = sb + 2 * TILE_B;
        uint32_t af[4][4];
        #pragma unroll
        for (int mi = 0; mi < 4; mi++) {
            int rowA = wm * 64 + mi * 16 + r;
            uint32_t off = rowA * PITCH_B + ((sel ^ ((rowA >> 2) & 1)) << 4);
            ldsm_x4(af[mi][0], af[mi][1], af[mi][2], af[mi][3], sA + off);
        }
        uint32_t bh[2][4], bl[2][4];
        #pragma unroll
        for (int nj = 0; nj < 2; nj++) {
            int rowB = wn * 32 + nj * 16 + r;
            uint32_t off = rowB * PITCH_B + ((sel ^ ((rowB >> 2) & 1)) << 4);
            ldsm_x4(bh[nj][0], bh[nj][1], bh[nj][2], bh[nj][3], sBh + off);
            ldsm_x4(bl[nj][0], bl[nj][1], bl[nj][2], bl[nj][3], sBl + off);
        }
        #pragma unroll
        for (int mi = 0; mi < 4; mi++) {
            #pragma unroll
            for (int nn = 0; nn < 4; nn++) {
                int nj = nn >> 1, hi8 = nn & 1;
                mma_fp16(acc[mi][nn], af[mi], bh[nj][hi8], bh[nj][hi8 + 2]);
                mma_fp16(acc[mi][nn], af[mi], bl[nj][hi8], bl[nj][hi8 + 2]);
            }
        }
    };

    load_pair(0, 0);

    for (int p = 0; p < npair; p++) {
        if (p + 1 < npair) load_pair((p + 1) & 1, p + 1);
        if (p + 1 < npair) { CP_WAIT(1); } else { CP_WAIT(0); }
        __syncthreads();
        uint32_t sb = sbase + (p & 1) * STAGE_B;
        compute_slab(sb);
        compute_slab(sb + SLAB_B);
        __syncthreads();
    }

    // epilogue
    int qr = lane >> 2, qc = lane & 3;
    #pragma unroll
    for (int nn = 0; nn < 4; nn++) {
        int col = n0 + wn * 32 + (nn >> 1) * 16 + (nn & 1) * 8 + qc * 2;
        float bz0 = __ldg(&bias[col]), bz1 = __ldg(&bias[col + 1]);
        #pragma unroll
        for (int mi = 0; mi < 4; mi++) {
            int row0 = m0 + wm * 64 + mi * 16 + qr;
            if (row0 < M) {
                float v0 = fmaxf(acc[mi][nn][0] + bz0, 0.f);
                float v1 = fmaxf(acc[mi][nn][1] + bz1, 0.f);
                if (POOL) {
                    int g = __ldg(&batch[row0]);
                    atomicAdd(&g_sums[g * HID + col],     v0);
                    atomicAdd(&g_sums[g * HID + col + 1], v1);
                } else {
                    *(float2*)(C + (size_t)row0 * 256 + col) = make_float2(v0, v1);
                }
            }
            int row1 = row0 + 8;
            if (row1 < M) {
                float v2 = fmaxf(acc[mi][nn][2] + bz0, 0.f);
                float v3 = fmaxf(acc[mi][nn][3] + bz1, 0.f);
                if (POOL) {
                    int g = __ldg(&batch[row1]);
                    atomicAdd(&g_sums[g * HID + col],     v2);
                    atomicAdd(&g_sums[g * HID + col + 1], v3);
                } else {
                    *(float2*)(C + (size_t)row1 * 256 + col) = make_float2(v2, v3);
                }
            }
        }
    }
}

// ---------------------------------------------------------------------------
// 7. head: mean, concat, fc1(relu), fc2 -> out[G,16]
__global__ void head_kernel(const float* __restrict__ molwt, const float* __restrict__ nrings,
                            const float* __restrict__ fcW1, const float* __restrict__ fcb1,
                            const float* __restrict__ fcW2, const float* __restrict__ fcb2,
                            float* __restrict__ out) {
    int g = blockIdx.x;
    __shared__ float hg[258];
    __shared__ float h1[196];
    int t = threadIdx.x;  // 256
    float c = fmaxf((float)g_gcnt[g], 1.0f);
    hg[t] = g_sums[g * HID + t] / c;
    if (t == 0) { hg[256] = molwt[g]; hg[257] = nrings[g]; }
    __syncthreads();
    if (t < 196) {
        float a = fcb1[t];
        #pragma unroll 4
        for (int k = 0; k < 258; k++) a += hg[k] * fcW1[k * 196 + t];
        h1[t] = fmaxf(a, 0.0f);
    }
    __syncthreads();
    if (t < 16) {
        float a = fcb2[t];
        #pragma unroll 4
        for (int k = 0; k < 196; k++) a += h1[k] * fcW2[k * 16 + t];
        out[g * 16 + t] = a;
    }
}

// ---------------------------------------------------------------------------
extern "C" void kernel_launch(void* const* d_in, const int* in_sizes, int n_in,
                              void* d_out, int out_size) {
    const float* x      = (const float*)d_in[0];
    const int*   ei     = (const int*)  d_in[1];
    const int*   batch  = (const int*)  d_in[2];
    const float* molwt  = (const float*)d_in[3];
    const float* nrings = (const float*)d_in[4];
    const float* W1 = (const float*)d_in[5];
    const float* b1 = (const float*)d_in[6];
    const float* W2 = (const float*)d_in[7];
    const float* b2 = (const float*)d_in[8];
    const float* W3 = (const float*)d_in[9];
    const float* b3 = (const float*)d_in[10];
    const float* fcW1 = (const float*)d_in[11];
    const float* fcb1 = (const float*)d_in[12];
    const float* fcW2 = (const float*)d_in[13];
    const float* fcb2 = (const float*)d_in[14];

    const int N = in_sizes[2];
    const int E = in_sizes[1] / 2;
    const int G = in_sizes[3];
    const int F_IN = in_sizes[0] / N;   // 128

    __half *A, *Wh1, *Wl1, *Wh2, *Wl2, *Wh3, *Wl3;
    float* bufB;
    cudaGetSymbolAddress((void**)&A, g_A);
    cudaGetSymbolAddress((void**)&bufB, g_bufB);
    cudaGetSymbolAddress((void**)&Wh1, g_Wh1);
    cudaGetSymbolAddress((void**)&Wl1, g_Wl1);
    cudaGetSymbolAddress((void**)&Wh2, g_Wh2);
    cudaGetSymbolAddress((void**)&Wl2, g_Wl2);
    cudaGetSymbolAddress((void**)&Wh3, g_Wh3);
    cudaGetSymbolAddress((void**)&Wl3, g_Wl3);

    const int GEMM_SMEM = 2 * STAGE_B;   // 49152
    cudaFuncSetAttribute(gemm_tc<false>, cudaFuncAttributeMaxDynamicSharedMemorySize, GEMM_SMEM);
    cudaFuncSetAttribute(gemm_tc<true >, cudaFuncAttributeMaxDynamicSharedMemorySize, GEMM_SMEM);

    // graph structure
    int nb = (N + 1023) / 1024;
    init_kernel<<<256, 256>>>(N, G);
    count_kernel<<<(E + 255) / 256, 256>>>(ei, E);
    gcnt_kernel<<<(N + 255) / 256, 256>>>(batch, N);
    scan_p1<<<nb, 1024>>>(N);
    scan_p2<<<1, 64>>>(nb, N);
    scan_p3<<<nb, 1024>>>(N);
    fill_kernel<<<(E + 255) / 256, 256>>>(ei, E);

    // weight splits (transposed, K-major, fp16 hi/lo)
    wsplit_kernel<<<(F_IN * 256 + 255) / 256, 256>>>(W1, Wh1, Wl1, F_IN, 256);
    wsplit_kernel<<<(256 * 256 + 255) / 256, 256>>>(W2, Wh2, Wl2, 256, 256);
    wsplit_kernel<<<(256 * 256 + 255) / 256, 256>>>(W3, Wh3, Wl3, 256, 256);

    dim3 ggrid(2, (N + 127) / 128);
    int aggblocks = (N + 7) / 8;   // 8 warps / block

    // layer 1
    agg_split_v2<128><<<aggblocks, 256>>>(x, A, N);
    gemm_tc<false><<<ggrid, 256, GEMM_SMEM>>>(A, Wh1, Wl1, b1, bufB, nullptr, N, F_IN);
    // layer 2
    agg_split_v2<256><<<aggblocks, 256>>>(bufB, A, N);
    gemm_tc<false><<<ggrid, 256, GEMM_SMEM>>>(A, Wh2, Wl2, b2, bufB, nullptr, N, HID);
    // layer 3 (pooling fused into epilogue)
    agg_split_v2<256><<<aggblocks, 256>>>(bufB, A, N);
    gemm_tc<true><<<ggrid, 256, GEMM_SMEM>>>(A, Wh3, Wl3, b3, nullptr, batch, N, HID);

    // pooling mean + head
    head_kernel<<<G, 256>>>(molwt, nrings, fcW1, fcb1, fcW2, fcb2, (float*)d_out);
}

// round 10
// speedup vs baseline: 1.6701x; 1.2802x over previous
#include <cuda_runtime.h>
#include <cuda_fp16.h>
#include <cstdint>
#include <math.h>

// Problem constants (fixed for this dataset)
#define MAXN 50000
#define MAXE 800000
#define MAXG 512
#define HID  256

// ---------------------------------------------------------------------------
// Scratch (__device__ globals: allocation-free per harness rules)
__device__ __half g_A[(size_t)MAXN * HID];            // agg output, fp16
__device__ __half g_H[(size_t)MAXN * HID];            // hidden state, fp16
__device__ float g_dis[MAXN];
__device__ int   g_counts[MAXN];
__device__ int   g_offs[MAXN + 1];
__device__ int   g_wptr[MAXN];
__device__ int   g_csr[MAXE];
__device__ float g_sums[MAXG * HID];
__device__ int   g_gcnt[MAXG];
__device__ int   g_bsum[64];
// transposed weights: [N=256 rows][K cols], K-major fp16
__device__ __half g_W1t[256 * 128];
__device__ __half g_W2t[256 * 256];
__device__ __half g_W3t[256 * 256];

// ---------------------------------------------------------------------------
// base-ISA tensor helpers (mma.sync / ldmatrix / cp.async)
__device__ __forceinline__ void ldsm_x4(uint32_t& r0, uint32_t& r1, uint32_t& r2, uint32_t& r3,
                                        uint32_t addr) {
    asm volatile("ldmatrix.sync.aligned.m8n8.x4.shared.b16 {%0,%1,%2,%3}, [%4];"
                 : "=r"(r0), "=r"(r1), "=r"(r2), "=r"(r3) : "r"(addr));
}
__device__ __forceinline__ void mma_fp16(float* c, const uint32_t* a, uint32_t b0, uint32_t b1) {
    asm volatile("mma.sync.aligned.m16n8k16.row.col.f32.f16.f16.f32 "
                 "{%0,%1,%2,%3}, {%4,%5,%6,%7}, {%8,%9}, {%0,%1,%2,%3};"
                 : "+f"(c[0]), "+f"(c[1]), "+f"(c[2]), "+f"(c[3])
                 : "r"(a[0]), "r"(a[1]), "r"(a[2]), "r"(a[3]), "r"(b0), "r"(b1));
}
__device__ __forceinline__ void cp_async16(uint32_t smem_addr, const void* gptr, uint32_t src_sz) {
    asm volatile("cp.async.cg.shared.global [%0], [%1], 16, %2;"
                 :: "r"(smem_addr), "l"(gptr), "r"(src_sz) : "memory");
}
#define CP_COMMIT() asm volatile("cp.async.commit_group;" ::: "memory")
#define CP_WAIT(n)  asm volatile("cp.async.wait_group %0;" :: "n"(n) : "memory")
__device__ __forceinline__ uint32_t smem_u32(const void* p) {
    uint32_t a;
    asm("{ .reg .u64 t; cvta.to.shared.u64 t, %1; cvt.u32.u64 %0, t; }" : "=r"(a) : "l"(p));
    return a;
}

// ---------------------------------------------------------------------------
// 0. zero-init
__global__ void init_kernel(int n_nodes, int n_graphs) {
    int i = blockIdx.x * blockDim.x + threadIdx.x;
    int total = n_nodes + n_graphs + n_graphs * HID;
    for (; i < total; i += gridDim.x * blockDim.x) {
        if (i < n_nodes) g_counts[i] = 0;
        else if (i < n_nodes + n_graphs) g_gcnt[i - n_nodes] = 0;
        else g_sums[i - n_nodes - n_graphs] = 0.0f;
    }
}
// 1. in-degree
__global__ void count_kernel(const int* __restrict__ ei, int E) {
    int e = blockIdx.x * blockDim.x + threadIdx.x;
    if (e < E) atomicAdd(&g_counts[ei[E + e]], 1);
}
// 1b. per-graph node counts
__global__ void gcnt_kernel(const int* __restrict__ batch, int N) {
    int i = blockIdx.x * blockDim.x + threadIdx.x;
    if (i < N) atomicAdd(&g_gcnt[batch[i]], 1);
}
// 2a. per-block reduce -> g_bsum
__global__ void scan_p1(int n) {
    int i = blockIdx.x * 1024 + threadIdx.x;
    int v = (i < n) ? g_counts[i] : 0;
    __shared__ int sw[32];
    int lane = threadIdx.x & 31, wid = threadIdx.x >> 5;
    int s = v;
    #pragma unroll
    for (int o = 16; o > 0; o >>= 1) s += __shfl_down_sync(0xffffffffu, s, o);
    if (lane == 0) sw[wid] = s;
    __syncthreads();
    if (wid == 0) {
        int t = sw[lane];
        #pragma unroll
        for (int o = 16; o > 0; o >>= 1) t += __shfl_down_sync(0xffffffffu, t, o);
        if (lane == 0) g_bsum[blockIdx.x] = t;
    }
}
// 2b. one block scans block sums
__global__ void scan_p2(int nb, int n) {
    int lane = threadIdx.x;  // 64 threads
    __shared__ int sm[64];
    int v = (lane < nb) ? g_bsum[lane] : 0;
    sm[lane] = v;
    __syncthreads();
    #pragma unroll
    for (int d = 1; d < 64; d <<= 1) {
        int t = (lane >= d) ? sm[lane - d] : 0;
        __syncthreads();
        sm[lane] += t;
        __syncthreads();
    }
    if (lane < nb) g_bsum[lane] = sm[lane] - v;
    if (lane == nb - 1) g_offs[n] = sm[lane];
}
// 2c. per-block inclusive scan + base -> offs/wptr/dis
__global__ void scan_p3(int n) {
    int base = g_bsum[blockIdx.x];
    int i = blockIdx.x * 1024 + threadIdx.x;
    int v = (i < n) ? g_counts[i] : 0;
    __shared__ int sw[32];
    int lane = threadIdx.x & 31, wid = threadIdx.x >> 5;
    int inc = v;
    #pragma unroll
    for (int o = 1; o < 32; o <<= 1) {
        int t = __shfl_up_sync(0xffffffffu, inc, o);
        if (lane >= o) inc += t;
    }
    if (lane == 31) sw[wid] = inc;
    __syncthreads();
    if (wid == 0) {
        int t = sw[lane];
        #pragma unroll
        for (int o = 1; o < 32; o <<= 1) {
            int u = __shfl_up_sync(0xffffffffu, t, o);
            if (lane >= o) t += u;
        }
        sw[lane] = t;
    }
    __syncthreads();
    int excl = base + inc - v + (wid > 0 ? sw[wid - 1] : 0);
    if (i < n) {
        g_offs[i] = excl;
        g_wptr[i] = excl;
        g_dis[i]  = rsqrtf(1.0f + (float)v);
    }
}
// 3. fill CSR
__global__ void fill_kernel(const int* __restrict__ ei, int E) {
    int e = blockIdx.x * blockDim.x + threadIdx.x;
    if (e < E) {
        int s = ei[e], d = ei[E + e];
        g_csr[atomicAdd(&g_wptr[d], 1)] = s;
    }
}

// ---------------------------------------------------------------------------
// 4a. warp-per-node aggregation, fp32 input (layer 1, F=128) -> fp16 out
__global__ void agg_f32(const float* __restrict__ h, __half* __restrict__ oh, int N) {
    const int F = 128;
    int node = blockIdx.x * (blockDim.x >> 5) + (threadIdx.x >> 5);
    int lane = threadIdx.x & 31;
    if (node >= N) return;

    float di = g_dis[node];
    const float4* hrow = (const float4*)(h + (size_t)node * F);
    float4 t0 = hrow[lane];
    float4 acc = make_float4(di * t0.x, di * t0.y, di * t0.z, di * t0.w);

    int e0 = g_offs[node], e1 = g_offs[node + 1];
    for (int base = e0; base < e1; base += 32) {
        int e = base + lane;
        int s = 0; float w = 0.0f;
        if (e < e1) { s = g_csr[e]; w = g_dis[s]; }
        int cnt = min(32, e1 - base);
        #pragma unroll 4
        for (int j = 0; j < cnt; j++) {
            int   sj = __shfl_sync(0xffffffffu, s, j);
            float wj = __shfl_sync(0xffffffffu, w, j);
            float4 t = ((const float4*)(h + (size_t)sj * F))[lane];
            acc.x += wj * t.x; acc.y += wj * t.y;
            acc.z += wj * t.z; acc.w += wj * t.w;
        }
    }
    __half2 h01 = __floats2half2_rn(di * acc.x, di * acc.y);
    __half2 h23 = __floats2half2_rn(di * acc.z, di * acc.w);
    uint2 u; u.x = *(uint32_t*)&h01; u.y = *(uint32_t*)&h23;
    *(uint2*)(oh + (size_t)node * F + lane * 4) = u;
}

// 4b. warp-per-node aggregation, fp16 input (layers 2-3, F=256) -> fp16 out
//     lane owns 8 contiguous halfs (one 16B load per row)
__global__ void agg_f16(const __half* __restrict__ h, __half* __restrict__ oh, int N) {
    const int F = 256;
    int node = blockIdx.x * (blockDim.x >> 5) + (threadIdx.x >> 5);
    int lane = threadIdx.x & 31;
    if (node >= N) return;

    float di = g_dis[node];
    float acc[8];
    {
        uint4 u = ((const uint4*)(h + (size_t)node * F))[lane];
        const __half2* hp = (const __half2*)&u;
        #pragma unroll
        for (int q = 0; q < 4; q++) {
            float2 f = __half22float2(hp[q]);
            acc[2*q]   = di * f.x;
            acc[2*q+1] = di * f.y;
        }
    }
    int e0 = g_offs[node], e1 = g_offs[node + 1];
    for (int base = e0; base < e1; base += 32) {
        int e = base + lane;
        int s = 0; float w = 0.0f;
        if (e < e1) { s = g_csr[e]; w = g_dis[s]; }
        int cnt = min(32, e1 - base);
        #pragma unroll 4
        for (int j = 0; j < cnt; j++) {
            int   sj = __shfl_sync(0xffffffffu, s, j);
            float wj = __shfl_sync(0xffffffffu, w, j);
            uint4 u = ((const uint4*)(h + (size_t)sj * F))[lane];
            const __half2* hp = (const __half2*)&u;
            #pragma unroll
            for (int q = 0; q < 4; q++) {
                float2 f = __half22float2(hp[q]);
                acc[2*q]   += wj * f.x;
                acc[2*q+1] += wj * f.y;
            }
        }
    }
    uint4 o;
    __half2 o0 = __floats2half2_rn(di * acc[0], di * acc[1]);
    __half2 o1 = __floats2half2_rn(di * acc[2], di * acc[3]);
    __half2 o2 = __floats2half2_rn(di * acc[4], di * acc[5]);
    __half2 o3 = __floats2half2_rn(di * acc[6], di * acc[7]);
    o.x = *(uint32_t*)&o0; o.y = *(uint32_t*)&o1;
    o.z = *(uint32_t*)&o2; o.w = *(uint32_t*)&o3;
    ((uint4*)(oh + (size_t)node * F))[lane] = o;
}

// 5. weight transpose: W[K,N] fp32 -> Wt[N,K] fp16 (K-major)
__global__ void wtrans_kernel(const float* __restrict__ W, __half* __restrict__ Wt,
                              int K, int N) {
    int idx = blockIdx.x * blockDim.x + threadIdx.x;
    if (idx < K * N) {
        int k = idx / N, n = idx % N;
        Wt[n * K + k] = __float2half_rn(W[idx]);
    }
}

// ---------------------------------------------------------------------------
// 6. pure-fp16 tensor-core GEMM: C = relu( A @ B^T + bias ), fp32 accumulate.
//    CTA 128x128, 256 thr, paired k16 slabs per stage (k=32), double buffer.
//    POOL=false: write __half C.  POOL=true: atomicAdd fp32 into g_sums.
#define PITCH_B 32
#define TILE_B  4096
#define SLAB_B  8192             // one k16 slab: A, B tiles
#define STAGE_B (2 * SLAB_B)

template <bool POOL>
__global__ void __launch_bounds__(256)
gemm_tc(const __half* __restrict__ A, const __half* __restrict__ B,
        const float* __restrict__ bias, __half* __restrict__ C,
        const int* __restrict__ batch, int M, int K) {
    extern __shared__ __align__(1024) char smem[];
    uint32_t sbase = smem_u32(smem);

    int tid = threadIdx.x;
    int wid = tid >> 5, lane = tid & 31;
    int wm = wid >> 2, wn = wid & 3;
    int m0 = blockIdx.y * 128, n0 = blockIdx.x * 128;

    float acc[4][4][4];
    #pragma unroll
    for (int i = 0; i < 4; i++)
        #pragma unroll
        for (int j = 0; j < 4; j++)
            #pragma unroll
            for (int q = 0; q < 4; q++) acc[i][j][q] = 0.0f;

    int npair = K >> 5;

    auto load_slab = [&](uint32_t sb, int k0) {
        #pragma unroll
        for (int i = 0; i < 2; i++) {
            int c = tid + i * 256;
            int tile = c >> 8, t = c & 255;
            int row = t >> 1, half = t & 1;
            uint32_t dst = sb + tile * TILE_B + row * PITCH_B +
                           ((half ^ ((row >> 2) & 1)) << 4);
            const __half* src;
            uint32_t sz = 16;
            if (tile == 0) {
                int gr = m0 + row;
                int cr = gr < M ? gr : (M - 1);
                src = A + (size_t)cr * K + k0 + half * 8;
                if (gr >= M) sz = 0;
            } else {
                src = B + (size_t)(n0 + row) * K + k0 + half * 8;
            }
            cp_async16(dst, src, sz);
        }
    };
    auto load_pair = [&](int stage, int p) {
        uint32_t sb = sbase + stage * STAGE_B;
        load_slab(sb,          p * 32);
        load_slab(sb + SLAB_B, p * 32 + 16);
        CP_COMMIT();
    };

    int r = lane & 15, sel = lane >> 4;

    auto compute_slab = [&](uint32_t sb) {
        uint32_t sA = sb, sB = sb + TILE_B;
        uint32_t af[4][4];
        #pragma unroll
        for (int mi = 0; mi < 4; mi++) {
            int rowA = wm * 64 + mi * 16 + r;
            uint32_t off = rowA * PITCH_B + ((sel ^ ((rowA >> 2) & 1)) << 4);
            ldsm_x4(af[mi][0], af[mi][1], af[mi][2], af[mi][3], sA + off);
        }
        uint32_t bf[2][4];
        #pragma unroll
        for (int nj = 0; nj < 2; nj++) {
            int rowB = wn * 32 + nj * 16 + r;
            uint32_t off = rowB * PITCH_B + ((sel ^ ((rowB >> 2) & 1)) << 4);
            ldsm_x4(bf[nj][0], bf[nj][1], bf[nj][2], bf[nj][3], sB + off);
        }
        #pragma unroll
        for (int mi = 0; mi < 4; mi++) {
            #pragma unroll
            for (int nn = 0; nn < 4; nn++) {
                int nj = nn >> 1, hi8 = nn & 1;
                mma_fp16(acc[mi][nn], af[mi], bf[nj][hi8], bf[nj][hi8 + 2]);
            }
        }
    };

    load_pair(0, 0);

    for (int p = 0; p < npair; p++) {
        if (p + 1 < npair) load_pair((p + 1) & 1, p + 1);
        if (p + 1 < npair) { CP_WAIT(1); } else { CP_WAIT(0); }
        __syncthreads();
        uint32_t sb = sbase + (p & 1) * STAGE_B;
        compute_slab(sb);
        compute_slab(sb + SLAB_B);
        __syncthreads();
    }

    // epilogue
    int qr = lane >> 2, qc = lane & 3;
    #pragma unroll
    for (int nn = 0; nn < 4; nn++) {
        int col = n0 + wn * 32 + (nn >> 1) * 16 + (nn & 1) * 8 + qc * 2;
        float bz0 = __ldg(&bias[col]), bz1 = __ldg(&bias[col + 1]);
        #pragma unroll
        for (int mi = 0; mi < 4; mi++) {
            int row0 = m0 + wm * 64 + mi * 16 + qr;
            if (row0 < M) {
                float v0 = fmaxf(acc[mi][nn][0] + bz0, 0.f);
                float v1 = fmaxf(acc[mi][nn][1] + bz1, 0.f);
                if (POOL) {
                    int g = __ldg(&batch[row0]);
                    atomicAdd(&g_sums[g * HID + col],     v0);
                    atomicAdd(&g_sums[g * HID + col + 1], v1);
                } else {
                    __half2 hv = __floats2half2_rn(v0, v1);
                    *(__half2*)(C + (size_t)row0 * 256 + col) = hv;
                }
            }
            int row1 = row0 + 8;
            if (row1 < M) {
                float v2 = fmaxf(acc[mi][nn][2] + bz0, 0.f);
                float v3 = fmaxf(acc[mi][nn][3] + bz1, 0.f);
                if (POOL) {
                    int g = __ldg(&batch[row1]);
                    atomicAdd(&g_sums[g * HID + col],     v2);
                    atomicAdd(&g_sums[g * HID + col + 1], v3);
                } else {
                    __half2 hv = __floats2half2_rn(v2, v3);
                    *(__half2*)(C + (size_t)row1 * 256 + col) = hv;
                }
            }
        }
    }
}

// ---------------------------------------------------------------------------
// 7. head: mean, concat, fc1(relu), fc2 -> out[G,16]
__global__ void head_kernel(const float* __restrict__ molwt, const float* __restrict__ nrings,
                            const float* __restrict__ fcW1, const float* __restrict__ fcb1,
                            const float* __restrict__ fcW2, const float* __restrict__ fcb2,
                            float* __restrict__ out) {
    int g = blockIdx.x;
    __shared__ float hg[258];
    __shared__ float h1[196];
    int t = threadIdx.x;  // 256
    float c = fmaxf((float)g_gcnt[g], 1.0f);
    hg[t] = g_sums[g * HID + t] / c;
    if (t == 0) { hg[256] = molwt[g]; hg[257] = nrings[g]; }
    __syncthreads();
    if (t < 196) {
        float a = fcb1[t];
        #pragma unroll 4
        for (int k = 0; k < 258; k++) a += hg[k] * fcW1[k * 196 + t];
        h1[t] = fmaxf(a, 0.0f);
    }
    __syncthreads();
    if (t < 16) {
        float a = fcb2[t];
        #pragma unroll 4
        for (int k = 0; k < 196; k++) a += h1[k] * fcW2[k * 16 + t];
        out[g * 16 + t] = a;
    }
}

// ---------------------------------------------------------------------------
extern "C" void kernel_launch(void* const* d_in, const int* in_sizes, int n_in,
                              void* d_out, int out_size) {
    const float* x      = (const float*)d_in[0];
    const int*   ei     = (const int*)  d_in[1];
    const int*   batch  = (const int*)  d_in[2];
    const float* molwt  = (const float*)d_in[3];
    const float* nrings = (const float*)d_in[4];
    const float* W1 = (const float*)d_in[5];
    const float* b1 = (const float*)d_in[6];
    const float* W2 = (const float*)d_in[7];
    const float* b2 = (const float*)d_in[8];
    const float* W3 = (const float*)d_in[9];
    const float* b3 = (const float*)d_in[10];
    const float* fcW1 = (const float*)d_in[11];
    const float* fcb1 = (const float*)d_in[12];
    const float* fcW2 = (const float*)d_in[13];
    const float* fcb2 = (const float*)d_in[14];

    const int N = in_sizes[2];
    const int E = in_sizes[1] / 2;
    const int G = in_sizes[3];
    const int F_IN = in_sizes[0] / N;   // 128

    __half *A, *H, *W1t, *W2t, *W3t;
    cudaGetSymbolAddress((void**)&A, g_A);
    cudaGetSymbolAddress((void**)&H, g_H);
    cudaGetSymbolAddress((void**)&W1t, g_W1t);
    cudaGetSymbolAddress((void**)&W2t, g_W2t);
    cudaGetSymbolAddress((void**)&W3t, g_W3t);

    const int GEMM_SMEM = 2 * STAGE_B;   // 32768
    cudaFuncSetAttribute(gemm_tc<false>, cudaFuncAttributeMaxDynamicSharedMemorySize, GEMM_SMEM);
    cudaFuncSetAttribute(gemm_tc<true >, cudaFuncAttributeMaxDynamicSharedMemorySize, GEMM_SMEM);

    // graph structure
    int nb = (N + 1023) / 1024;
    init_kernel<<<256, 256>>>(N, G);
    count_kernel<<<(E + 255) / 256, 256>>>(ei, E);
    gcnt_kernel<<<(N + 255) / 256, 256>>>(batch, N);
    scan_p1<<<nb, 1024>>>(N);
    scan_p2<<<1, 64>>>(nb, N);
    scan_p3<<<nb, 1024>>>(N);
    fill_kernel<<<(E + 255) / 256, 256>>>(ei, E);

    // weight transposes (fp16, K-major)
    wtrans_kernel<<<(F_IN * 256 + 255) / 256, 256>>>(W1, W1t, F_IN, 256);
    wtrans_kernel<<<(256 * 256 + 255) / 256, 256>>>(W2, W2t, 256, 256);
    wtrans_kernel<<<(256 * 256 + 255) / 256, 256>>>(W3, W3t, 256, 256);

    dim3 ggrid(2, (N + 127) / 128);
    int aggblocks = (N + 7) / 8;   // 8 warps / block

    // layer 1: fp32 x -> A fp16, GEMM -> H fp16
    agg_f32<<<aggblocks, 256>>>(x, A, N);
    gemm_tc<false><<<ggrid, 256, GEMM_SMEM>>>(A, W1t, b1, H, nullptr, N, F_IN);
    // layer 2: fp16 H -> A, GEMM -> H
    agg_f16<<<aggblocks, 256>>>(H, A, N);
    gemm_tc<false><<<ggrid, 256, GEMM_SMEM>>>(A, W2t, b2, H, nullptr, N, HID);
    // layer 3: fp16 H -> A, GEMM pools into g_sums
    agg_f16<<<aggblocks, 256>>>(H, A, N);
    gemm_tc<true><<<ggrid, 256, GEMM_SMEM>>>(A, W3t, b3, nullptr, batch, N, HID);

    // head
    head_kernel<<<G, 256>>>(molwt, nrings, fcW1, fcb1, fcW2, fcb2, (float*)d_out);
}

// round 11
// speedup vs baseline: 1.7038x; 1.0202x over previous
#include <cuda_runtime.h>
#include <cuda_fp16.h>
#include <cstdint>
#include <math.h>

// Problem constants (fixed for this dataset)
#define MAXN 50000
#define MAXE 800000
#define MAXG 512
#define HID  256

// ---------------------------------------------------------------------------
// Scratch (__device__ globals: allocation-free per harness rules)
__device__ __half g_A[(size_t)MAXN * HID];            // agg output, fp16
__device__ __half g_H[(size_t)MAXN * HID];            // hidden state, fp16
__device__ __half g_x16[(size_t)MAXN * 128];          // fp16 copy of input x
__device__ float g_dis[MAXN];
__device__ int   g_counts[MAXN];
__device__ int   g_offs[MAXN + 1];
__device__ int   g_wptr[MAXN];
__device__ int   g_csr[MAXE];
__device__ float g_sums[MAXG * HID];
__device__ int   g_gcnt[MAXG];
__device__ int   g_bsum[64];
// transposed weights: [N=256 rows][K cols], K-major fp16
__device__ __half g_W1t[256 * 128];
__device__ __half g_W2t[256 * 256];
__device__ __half g_W3t[256 * 256];

// ---------------------------------------------------------------------------
// base-ISA tensor helpers (mma.sync / ldmatrix / cp.async)
__device__ __forceinline__ void ldsm_x4(uint32_t& r0, uint32_t& r1, uint32_t& r2, uint32_t& r3,
                                        uint32_t addr) {
    asm volatile("ldmatrix.sync.aligned.m8n8.x4.shared.b16 {%0,%1,%2,%3}, [%4];"
                 : "=r"(r0), "=r"(r1), "=r"(r2), "=r"(r3) : "r"(addr));
}
__device__ __forceinline__ void mma_fp16(float* c, const uint32_t* a, uint32_t b0, uint32_t b1) {
    asm volatile("mma.sync.aligned.m16n8k16.row.col.f32.f16.f16.f32 "
                 "{%0,%1,%2,%3}, {%4,%5,%6,%7}, {%8,%9}, {%0,%1,%2,%3};"
                 : "+f"(c[0]), "+f"(c[1]), "+f"(c[2]), "+f"(c[3])
                 : "r"(a[0]), "r"(a[1]), "r"(a[2]), "r"(a[3]), "r"(b0), "r"(b1));
}
__device__ __forceinline__ void cp_async16(uint32_t smem_addr, const void* gptr, uint32_t src_sz) {
    asm volatile("cp.async.cg.shared.global [%0], [%1], 16, %2;"
                 :: "r"(smem_addr), "l"(gptr), "r"(src_sz) : "memory");
}
#define CP_COMMIT() asm volatile("cp.async.commit_group;" ::: "memory")
#define CP_WAIT(n)  asm volatile("cp.async.wait_group %0;" :: "n"(n) : "memory")
__device__ __forceinline__ uint32_t smem_u32(const void* p) {
    uint32_t a;
    asm("{ .reg .u64 t; cvta.to.shared.u64 t, %1; cvt.u32.u64 %0, t; }" : "=r"(a) : "l"(p));
    return a;
}

// ---------------------------------------------------------------------------
// 0. zero-init
__global__ void init_kernel(int n_nodes, int n_graphs) {
    int i = blockIdx.x * blockDim.x + threadIdx.x;
    int total = n_nodes + n_graphs + n_graphs * HID;
    for (; i < total; i += gridDim.x * blockDim.x) {
        if (i < n_nodes) g_counts[i] = 0;
        else if (i < n_nodes + n_graphs) g_gcnt[i - n_nodes] = 0;
        else g_sums[i - n_nodes - n_graphs] = 0.0f;
    }
}
// 1. in-degree counts + per-graph node counts (merged)
__global__ void count_gcnt(const int* __restrict__ ei, const int* __restrict__ batch,
                           int E, int N) {
    int i = blockIdx.x * blockDim.x + threadIdx.x;
    if (i < E) atomicAdd(&g_counts[ei[E + i]], 1);
    else if (i < E + N) atomicAdd(&g_gcnt[batch[i - E]], 1);
}
// 1b. convert input x to fp16 (N*128 elems, 4 per thread)
__global__ void xhalf_kernel(const float* __restrict__ x, __half* __restrict__ o, int total4) {
    int i = blockIdx.x * blockDim.x + threadIdx.x;
    if (i < total4) {
        float4 f = ((const float4*)x)[i];
        __half2 a = __floats2half2_rn(f.x, f.y);
        __half2 b = __floats2half2_rn(f.z, f.w);
        uint2 u; u.x = *(uint32_t*)&a; u.y = *(uint32_t*)&b;
        ((uint2*)o)[i] = u;
    }
}
// 2a. per-block reduce -> g_bsum
__global__ void scan_p1(int n) {
    int i = blockIdx.x * 1024 + threadIdx.x;
    int v = (i < n) ? g_counts[i] : 0;
    __shared__ int sw[32];
    int lane = threadIdx.x & 31, wid = threadIdx.x >> 5;
    int s = v;
    #pragma unroll
    for (int o = 16; o > 0; o >>= 1) s += __shfl_down_sync(0xffffffffu, s, o);
    if (lane == 0) sw[wid] = s;
    __syncthreads();
    if (wid == 0) {
        int t = sw[lane];
        #pragma unroll
        for (int o = 16; o > 0; o >>= 1) t += __shfl_down_sync(0xffffffffu, t, o);
        if (lane == 0) g_bsum[blockIdx.x] = t;
    }
}
// 2b. one block scans block sums
__global__ void scan_p2(int nb, int n) {
    int lane = threadIdx.x;  // 64 threads
    __shared__ int sm[64];
    int v = (lane < nb) ? g_bsum[lane] : 0;
    sm[lane] = v;
    __syncthreads();
    #pragma unroll
    for (int d = 1; d < 64; d <<= 1) {
        int t = (lane >= d) ? sm[lane - d] : 0;
        __syncthreads();
        sm[lane] += t;
        __syncthreads();
    }
    if (lane < nb) g_bsum[lane] = sm[lane] - v;
    if (lane == nb - 1) g_offs[n] = sm[lane];
}
// 2c. per-block inclusive scan + base -> offs/wptr/dis
__global__ void scan_p3(int n) {
    int base = g_bsum[blockIdx.x];
    int i = blockIdx.x * 1024 + threadIdx.x;
    int v = (i < n) ? g_counts[i] : 0;
    __shared__ int sw[32];
    int lane = threadIdx.x & 31, wid = threadIdx.x >> 5;
    int inc = v;
    #pragma unroll
    for (int o = 1; o < 32; o <<= 1) {
        int t = __shfl_up_sync(0xffffffffu, inc, o);
        if (lane >= o) inc += t;
    }
    if (lane == 31) sw[wid] = inc;
    __syncthreads();
    if (wid == 0) {
        int t = sw[lane];
        #pragma unroll
        for (int o = 1; o < 32; o <<= 1) {
            int u = __shfl_up_sync(0xffffffffu, t, o);
            if (lane >= o) t += u;
        }
        sw[lane] = t;
    }
    __syncthreads();
    int excl = base + inc - v + (wid > 0 ? sw[wid - 1] : 0);
    if (i < n) {
        g_offs[i] = excl;
        g_wptr[i] = excl;
        g_dis[i]  = rsqrtf(1.0f + (float)v);
    }
}
// 3. fill CSR
__global__ void fill_kernel(const int* __restrict__ ei, int E) {
    int e = blockIdx.x * blockDim.x + threadIdx.x;
    if (e < E) {
        int s = ei[e], d = ei[E + e];
        g_csr[atomicAdd(&g_wptr[d], 1)] = s;
    }
}

// ---------------------------------------------------------------------------
// 4. warp-per-node aggregation on fp16 rows -> fp16 out. F in {128, 256}.
template <int F>
__global__ void agg_f16(const __half* __restrict__ h, __half* __restrict__ oh, int N) {
    constexpr int HPL = F / 32;      // halfs per lane: 4 (F=128) or 8 (F=256)
    constexpr int W2L = HPL / 2;     // half2 words per lane
    int node = blockIdx.x * (blockDim.x >> 5) + (threadIdx.x >> 5);
    int lane = threadIdx.x & 31;
    if (node >= N) return;

    float di = g_dis[node];
    float acc[HPL];
    {
        uint32_t v[W2L];
        if constexpr (F == 128) {
            uint2 u = ((const uint2*)(h + (size_t)node * F))[lane];
            v[0] = u.x; v[1] = u.y;
        } else {
            uint4 u = ((const uint4*)(h + (size_t)node * F))[lane];
            v[0] = u.x; v[1] = u.y; v[2] = u.z; v[3] = u.w;
        }
        #pragma unroll
        for (int q = 0; q < W2L; q++) {
            float2 f = __half22float2(*(__half2*)&v[q]);
            acc[2*q]   = di * f.x;
            acc[2*q+1] = di * f.y;
        }
    }
    int e0 = g_offs[node], e1 = g_offs[node + 1];
    for (int base = e0; base < e1; base += 32) {
        int e = base + lane;
        int s = 0; float w = 0.0f;
        if (e < e1) { s = g_csr[e]; w = g_dis[s]; }
        int cnt = min(32, e1 - base);
        #pragma unroll 4
        for (int j = 0; j < cnt; j++) {
            int   sj = __shfl_sync(0xffffffffu, s, j);
            float wj = __shfl_sync(0xffffffffu, w, j);
            uint32_t v[W2L];
            if constexpr (F == 128) {
                uint2 u = ((const uint2*)(h + (size_t)sj * F))[lane];
                v[0] = u.x; v[1] = u.y;
            } else {
                uint4 u = ((const uint4*)(h + (size_t)sj * F))[lane];
                v[0] = u.x; v[1] = u.y; v[2] = u.z; v[3] = u.w;
            }
            #pragma unroll
            for (int q = 0; q < W2L; q++) {
                float2 f = __half22float2(*(__half2*)&v[q]);
                acc[2*q]   += wj * f.x;
                acc[2*q+1] += wj * f.y;
            }
        }
    }
    uint32_t o[W2L];
    #pragma unroll
    for (int q = 0; q < W2L; q++) {
        __half2 hv = __floats2half2_rn(di * acc[2*q], di * acc[2*q+1]);
        o[q] = *(uint32_t*)&hv;
    }
    if constexpr (F == 128) {
        uint2 u; u.x = o[0]; u.y = o[1];
        ((uint2*)(oh + (size_t)node * F))[lane] = u;
    } else {
        uint4 u; u.x = o[0]; u.y = o[1]; u.z = o[2]; u.w = o[3];
        ((uint4*)(oh + (size_t)node * F))[lane] = u;
    }
}

// 5. all three weight transposes in one launch: W[K,N] fp32 -> Wt[N,K] fp16
__global__ void wtrans_all(const float* __restrict__ W1, const float* __restrict__ W2,
                           const float* __restrict__ W3, int K1) {
    int i = blockIdx.x * blockDim.x + threadIdx.x;
    int sz1 = K1 * 256, sz23 = 256 * 256;
    const float* W; __half* Wt; int idx, K;
    if (i < sz1)               { W = W1; Wt = g_W1t; idx = i;              K = K1;  }
    else if (i < sz1 + sz23)   { W = W2; Wt = g_W2t; idx = i - sz1;        K = 256; }
    else if (i < sz1 + 2*sz23) { W = W3; Wt = g_W3t; idx = i - sz1 - sz23; K = 256; }
    else return;
    int k = idx / 256, n = idx % 256;
    Wt[n * K + k] = __float2half_rn(W[idx]);
}

// ---------------------------------------------------------------------------
// 6. pure-fp16 tensor-core GEMM: C = relu( A @ B^T + bias ), fp32 accumulate.
//    CTA 128x128, 256 thr, paired k16 slabs per stage (k=32), double buffer.
#define PITCH_B 32
#define TILE_B  4096
#define SLAB_B  8192             // one k16 slab: A, B tiles
#define STAGE_B (2 * SLAB_B)

template <bool POOL>
__global__ void __launch_bounds__(256)
gemm_tc(const __half* __restrict__ A, const __half* __restrict__ B,
        const float* __restrict__ bias, __half* __restrict__ C,
        const int* __restrict__ batch, int M, int K) {
    extern __shared__ __align__(1024) char smem[];
    uint32_t sbase = smem_u32(smem);

    int tid = threadIdx.x;
    int wid = tid >> 5, lane = tid & 31;
    int wm = wid >> 2, wn = wid & 3;
    int m0 = blockIdx.y * 128, n0 = blockIdx.x * 128;

    float acc[4][4][4];
    #pragma unroll
    for (int i = 0; i < 4; i++)
        #pragma unroll
        for (int j = 0; j < 4; j++)
            #pragma unroll
            for (int q = 0; q < 4; q++) acc[i][j][q] = 0.0f;

    int npair = K >> 5;

    auto load_slab = [&](uint32_t sb, int k0) {
        #pragma unroll
        for (int i = 0; i < 2; i++) {
            int c = tid + i * 256;
            int tile = c >> 8, t = c & 255;
            int row = t >> 1, half = t & 1;
            uint32_t dst = sb + tile * TILE_B + row * PITCH_B +
                           ((half ^ ((row >> 2) & 1)) << 4);
            const __half* src;
            uint32_t sz = 16;
            if (tile == 0) {
                int gr = m0 + row;
                int cr = gr < M ? gr : (M - 1);
                src = A + (size_t)cr * K + k0 + half * 8;
                if (gr >= M) sz = 0;
            } else {
                src = B + (size_t)(n0 + row) * K + k0 + half * 8;
            }
            cp_async16(dst, src, sz);
        }
    };
    auto load_pair = [&](int stage, int p) {
        uint32_t sb = sbase + stage * STAGE_B;
        load_slab(sb,          p * 32);
        load_slab(sb + SLAB_B, p * 32 + 16);
        CP_COMMIT();
    };

    int r = lane & 15, sel = lane >> 4;

    auto compute_slab = [&](uint32_t sb) {
        uint32_t sA = sb, sB = sb + TILE_B;
        uint32_t af[4][4];
        #pragma unroll
        for (int mi = 0; mi < 4; mi++) {
            int rowA = wm * 64 + mi * 16 + r;
            uint32_t off = rowA * PITCH_B + ((sel ^ ((rowA >> 2) & 1)) << 4);
            ldsm_x4(af[mi][0], af[mi][1], af[mi][2], af[mi][3], sA + off);
        }
        uint32_t bf[2][4];
        #pragma unroll
        for (int nj = 0; nj < 2; nj++) {
            int rowB = wn * 32 + nj * 16 + r;
            uint32_t off = rowB * PITCH_B + ((sel ^ ((rowB >> 2) & 1)) << 4);
            ldsm_x4(bf[nj][0], bf[nj][1], bf[nj][2], bf[nj][3], sB + off);
        }
        #pragma unroll
        for (int mi = 0; mi < 4; mi++) {
            #pragma unroll
            for (int nn = 0; nn < 4; nn++) {
                int nj = nn >> 1, hi8 = nn & 1;
                mma_fp16(acc[mi][nn], af[mi], bf[nj][hi8], bf[nj][hi8 + 2]);
            }
        }
    };

    load_pair(0, 0);

    for (int p = 0; p < npair; p++) {
        if (p + 1 < npair) load_pair((p + 1) & 1, p + 1);
        if (p + 1 < npair) { CP_WAIT(1); } else { CP_WAIT(0); }
        __syncthreads();
        uint32_t sb = sbase + (p & 1) * STAGE_B;
        compute_slab(sb);
        compute_slab(sb + SLAB_B);
        __syncthreads();
    }

    // epilogue
    int qr = lane >> 2, qc = lane & 3;
    #pragma unroll
    for (int nn = 0; nn < 4; nn++) {
        int col = n0 + wn * 32 + (nn >> 1) * 16 + (nn & 1) * 8 + qc * 2;
        float bz0 = __ldg(&bias[col]), bz1 = __ldg(&bias[col + 1]);
        #pragma unroll
        for (int mi = 0; mi < 4; mi++) {
            int row0 = m0 + wm * 64 + mi * 16 + qr;
            if (row0 < M) {
                float v0 = fmaxf(acc[mi][nn][0] + bz0, 0.f);
                float v1 = fmaxf(acc[mi][nn][1] + bz1, 0.f);
                if (POOL) {
                    int g = __ldg(&batch[row0]);
                    atomicAdd(&g_sums[g * HID + col],     v0);
                    atomicAdd(&g_sums[g * HID + col + 1], v1);
                } else {
                    __half2 hv = __floats2half2_rn(v0, v1);
                    *(__half2*)(C + (size_t)row0 * 256 + col) = hv;
                }
            }
            int row1 = row0 + 8;
            if (row1 < M) {
                float v2 = fmaxf(acc[mi][nn][2] + bz0, 0.f);
                float v3 = fmaxf(acc[mi][nn][3] + bz1, 0.f);
                if (POOL) {
                    int g = __ldg(&batch[row1]);
                    atomicAdd(&g_sums[g * HID + col],     v2);
                    atomicAdd(&g_sums[g * HID + col + 1], v3);
                } else {
                    __half2 hv = __floats2half2_rn(v2, v3);
                    *(__half2*)(C + (size_t)row1 * 256 + col) = hv;
                }
            }
        }
    }
}

// ---------------------------------------------------------------------------
// 7. head: mean, concat, fc1(relu), fc2 -> out[G,16]
__global__ void head_kernel(const float* __restrict__ molwt, const float* __restrict__ nrings,
                            const float* __restrict__ fcW1, const float* __restrict__ fcb1,
                            const float* __restrict__ fcW2, const float* __restrict__ fcb2,
                            float* __restrict__ out) {
    int g = blockIdx.x;
    __shared__ float hg[258];
    __shared__ float h1[196];
    int t = threadIdx.x;  // 256
    float c = fmaxf((float)g_gcnt[g], 1.0f);
    hg[t] = g_sums[g * HID + t] / c;
    if (t == 0) { hg[256] = molwt[g]; hg[257] = nrings[g]; }
    __syncthreads();
    if (t < 196) {
        float a = fcb1[t];
        #pragma unroll 4
        for (int k = 0; k < 258; k++) a += hg[k] * fcW1[k * 196 + t];
        h1[t] = fmaxf(a, 0.0f);
    }
    __syncthreads();
    if (t < 16) {
        float a = fcb2[t];
        #pragma unroll 4
        for (int k = 0; k < 196; k++) a += h1[k] * fcW2[k * 16 + t];
        out[g * 16 + t] = a;
    }
}

// ---------------------------------------------------------------------------
extern "C" void kernel_launch(void* const* d_in, const int* in_sizes, int n_in,
                              void* d_out, int out_size) {
    const float* x      = (const float*)d_in[0];
    const int*   ei     = (const int*)  d_in[1];
    const int*   batch  = (const int*)  d_in[2];
    const float* molwt  = (const float*)d_in[3];
    const float* nrings = (const float*)d_in[4];
    const float* W1 = (const float*)d_in[5];
    const float* b1 = (const float*)d_in[6];
    const float* W2 = (const float*)d_in[7];
    const float* b2 = (const float*)d_in[8];
    const float* W3 = (const float*)d_in[9];
    const float* b3 = (const float*)d_in[10];
    const float* fcW1 = (const float*)d_in[11];
    const float* fcb1 = (const float*)d_in[12];
    const float* fcW2 = (const float*)d_in[13];
    const float* fcb2 = (const float*)d_in[14];

    const int N = in_sizes[2];
    const int E = in_sizes[1] / 2;
    const int G = in_sizes[3];
    const int F_IN = in_sizes[0] / N;   // 128

    __half *A, *H, *X16, *W1t, *W2t, *W3t;
    cudaGetSymbolAddress((void**)&A, g_A);
    cudaGetSymbolAddress((void**)&H, g_H);
    cudaGetSymbolAddress((void**)&X16, g_x16);
    cudaGetSymbolAddress((void**)&W1t, g_W1t);
    cudaGetSymbolAddress((void**)&W2t, g_W2t);
    cudaGetSymbolAddress((void**)&W3t, g_W3t);

    const int GEMM_SMEM = 2 * STAGE_B;   // 32768
    cudaFuncSetAttribute(gemm_tc<false>, cudaFuncAttributeMaxDynamicSharedMemorySize, GEMM_SMEM);
    cudaFuncSetAttribute(gemm_tc<true >, cudaFuncAttributeMaxDynamicSharedMemorySize, GEMM_SMEM);

    int nb = (N + 1023) / 1024;
    dim3 ggrid(2, (N + 127) / 128);
    int aggblocks = (N + 7) / 8;   // 8 warps / block

    // setup
    init_kernel<<<256, 256>>>(N, G);
    count_gcnt<<<(E + N + 255) / 256, 256>>>(ei, batch, E, N);
    xhalf_kernel<<<(N * F_IN / 4 + 255) / 256, 256>>>(x, X16, N * F_IN / 4);
    scan_p1<<<nb, 1024>>>(N);
    scan_p2<<<1, 64>>>(nb, N);
    scan_p3<<<nb, 1024>>>(N);
    fill_kernel<<<(E + 255) / 256, 256>>>(ei, E);
    int wtot = F_IN * 256 + 2 * 256 * 256;
    wtrans_all<<<(wtot + 255) / 256, 256>>>(W1, W2, W3, F_IN);

    // layer 1: fp16 x -> A, GEMM -> H
    agg_f16<128><<<aggblocks, 256>>>(X16, A, N);
    gemm_tc<false><<<ggrid, 256, GEMM_SMEM>>>(A, W1t, b1, H, nullptr, N, F_IN);
    // layer 2
    agg_f16<256><<<aggblocks, 256>>>(H, A, N);
    gemm_tc<false><<<ggrid, 256, GEMM_SMEM>>>(A, W2t, b2, H, nullptr, N, HID);
    // layer 3 (pooling fused into epilogue)
    agg_f16<256><<<aggblocks, 256>>>(H, A, N);
    gemm_tc<true><<<ggrid, 256, GEMM_SMEM>>>(A, W3t, b3, nullptr, batch, N, HID);

    // head
    head_kernel<<<G, 256>>>(molwt, nrings, fcW1, fcb1, fcW2, fcb2, (float*)d_out);
}